// round 10
// baseline (speedup 1.0000x reference)
#include <cuda_runtime.h>
#include <cuda_fp16.h>
#include <cstdint>

#define B_  4096
#define N_  49
#define H_  8
#define NW_ 64
#define MT  (B_ * N_)              // 200704 rows
#define KSP 512                    // 2-term split K (2 * 256)
#define SZ_AO ((size_t)MT * 256)
#define NN2 (N_ * N_)              // 2401

#define SCALE_F 0.17677669529663687f

// ---------------- scratch (device globals; no runtime alloc) ----------------
__device__ __half g_A[2][(size_t)MT * KSP];     // input split [hi, lo] fp16
__device__ __half g_Wqkv[2][768 * 256];         // Wt[n][k] fp16
__device__ __half g_Wproj[2][256 * 256];
__device__ float  g_lin[2][(size_t)MT * 768];   // qkv linear out (q|k|v)
__device__ __half g_aob[2][(size_t)MT * KSP];   // attn out split [hi, lo]
__device__ float  g_bm[NW_ * H_ * NN2];         // combined bias+mask

// ---------------- GEMM config (R7 proven config — do not touch) ----------------
#define BM 128
#define BN 128
#define SA_STR 40
#define SB_STR 264

struct GSmem {
    __align__(16) __half B[BN * SB_STR];
    __align__(16) __half A[4][BM * SA_STR];
};
#define SMEM_SZ ((int)sizeof(GSmem))

__device__ __forceinline__ void cp16(uint32_t dst, const void* src) {
    asm volatile("cp.async.cg.shared.global [%0], [%1], 16;" :: "r"(dst), "l"(src));
}
__device__ __forceinline__ void cp_commit() {
    asm volatile("cp.async.commit_group;" ::: "memory");
}
template<int NN> __device__ __forceinline__ void cp_wait() {
    asm volatile("cp.async.wait_group %0;" :: "n"(NN) : "memory");
}

__device__ __forceinline__ void mma16816(float* d, const uint32_t* a, const uint32_t* b) {
    asm volatile(
        "mma.sync.aligned.m16n8k16.row.col.f32.f16.f16.f32 "
        "{%0,%1,%2,%3}, {%4,%5,%6,%7}, {%8,%9}, {%0,%1,%2,%3};"
        : "+f"(d[0]), "+f"(d[1]), "+f"(d[2]), "+f"(d[3])
        : "r"(a[0]), "r"(a[1]), "r"(a[2]), "r"(a[3]), "r"(b[0]), "r"(b[1]));
}

#define LDSM_X4(r, addr)                                                     \
    asm volatile("ldmatrix.sync.aligned.m8n8.x4.shared.b16 {%0,%1,%2,%3}, [%4];" \
        : "=r"((r)[0]), "=r"((r)[1]), "=r"((r)[2]), "=r"((r)[3]) : "r"(addr))

__device__ __forceinline__ void gemm_main(
    GSmem& sm, const __half* __restrict__ A, const __half* __restrict__ W,
    int bm, int bn, float acc[4][4][4])
{
    const int tid = threadIdx.x;
    const uint32_t sB = (uint32_t)__cvta_generic_to_shared(sm.B);
    const uint32_t sA = (uint32_t)__cvta_generic_to_shared(sm.A);

    #pragma unroll
    for (int i = 0; i < 16; i++) {
        int idx = tid + i * 256;
        int r = idx >> 5, g = idx & 31;
        cp16(sB + (uint32_t)(r * SB_STR + g * 8) * 2,
             W + (size_t)(bn + r) * 256 + g * 8);
    }
    cp_commit();

    auto issueA = [&](int c) {
        uint32_t dst = sA + (uint32_t)((c & 3) * BM * SA_STR) * 2;
        #pragma unroll
        for (int i = 0; i < 2; i++) {
            int idx = tid + i * 256;
            int r = idx >> 2, g = idx & 3;
            cp16(dst + (uint32_t)(r * SA_STR + g * 8) * 2,
                 A + (size_t)(bm + r) * KSP + c * 32 + g * 8);
        }
        cp_commit();
    };
    issueA(0); issueA(1); issueA(2);

    const int lane = tid & 31;
    const int wm = (tid >> 5) & 1, wn = tid >> 6;

    const int a_row = wm * 64 + (lane & 7) + ((lane >> 3) & 1) * 8;
    const int a_col = (lane >> 4) * 8;
    const int b_row = wn * 32 + (lane >> 4) * 8 + (lane & 7);
    const int b_col = ((lane >> 3) & 1) * 8;

    auto compute = [&](int c) {
        const uint32_t aBase = sA + (uint32_t)((c & 3) * BM * SA_STR) * 2;
        const uint32_t bBase = sB + (uint32_t)((c & 7) * 32) * 2;
        #pragma unroll
        for (int ks = 0; ks < 2; ks++) {
            const int kb = ks * 16;
            uint32_t af[4][4], bf[2][4];
            #pragma unroll
            for (int mt = 0; mt < 4; mt++)
                LDSM_X4(af[mt],
                        aBase + (uint32_t)((a_row + mt * 16) * SA_STR + kb + a_col) * 2);
            #pragma unroll
            for (int pr = 0; pr < 2; pr++)
                LDSM_X4(bf[pr],
                        bBase + (uint32_t)((b_row + pr * 16) * SB_STR + kb + b_col) * 2);
            #pragma unroll
            for (int mt = 0; mt < 4; mt++)
                #pragma unroll
                for (int nt = 0; nt < 4; nt++)
                    mma16816(acc[mt][nt], af[mt], &bf[nt >> 1][(nt & 1) * 2]);
        }
    };

    for (int c = 0; c < 13; c++) {
        cp_wait<2>();
        __syncthreads();
        issueA(c + 3);
        compute(c);
    }
    cp_wait<2>(); __syncthreads(); compute(13);
    cp_wait<1>(); __syncthreads(); compute(14);
    cp_wait<0>(); __syncthreads(); compute(15);
}

// ---------------- GEMM kernels ----------------
__global__ __launch_bounds__(256, 2) void qkv_hmma(
    const float* __restrict__ b0, const float* __restrict__ b1)
{
    extern __shared__ char smem_raw[];
    GSmem& sm = *(GSmem*)smem_raw;
    const int stream = blockIdx.z;
    const int bn = blockIdx.x * BN;
    const int bm = blockIdx.y * BM;

    float acc[4][4][4] = {};
    gemm_main(sm, g_A[stream], g_Wqkv[stream], bm, bn, acc);

    const float* __restrict__ bias = stream ? b1 : b0;
    float* __restrict__ O = g_lin[stream];
    const int lane = threadIdx.x & 31;
    const int wm = (threadIdx.x >> 5) & 1, wn = threadIdx.x >> 6;
    const float sc = (bn < 256) ? SCALE_F : 1.0f;

    #pragma unroll
    for (int mt = 0; mt < 4; mt++) {
        const int r = bm + wm * 64 + mt * 16 + (lane >> 2);
        #pragma unroll
        for (int nt = 0; nt < 4; nt++) {
            const int col = bn + wn * 32 + nt * 8 + (lane & 3) * 2;
            const float bx = bias[col], by = bias[col + 1];
            float2 v0 = { (acc[mt][nt][0] + bx) * sc, (acc[mt][nt][1] + by) * sc };
            float2 v1 = { (acc[mt][nt][2] + bx) * sc, (acc[mt][nt][3] + by) * sc };
            *(float2*)&O[(size_t)r * 768 + col]       = v0;
            *(float2*)&O[(size_t)(r + 8) * 768 + col] = v1;
        }
    }
}

__global__ __launch_bounds__(256, 2) void proj_hmma(
    const float* __restrict__ bp0, const float* __restrict__ bp1,
    float* __restrict__ out)
{
    extern __shared__ char smem_raw[];
    GSmem& sm = *(GSmem*)smem_raw;
    const int p = blockIdx.z;
    const int bn = blockIdx.x * BN;
    const int bm = blockIdx.y * BM;

    float acc[4][4][4] = {};
    gemm_main(sm, g_aob[p], g_Wproj[p], bm, bn, acc);

    const float* __restrict__ bias = p ? bp1 : bp0;
    float* __restrict__ O = out + (size_t)p * SZ_AO;
    const int lane = threadIdx.x & 31;
    const int wm = (threadIdx.x >> 5) & 1, wn = threadIdx.x >> 6;

    #pragma unroll
    for (int mt = 0; mt < 4; mt++) {
        const int r = bm + wm * 64 + mt * 16 + (lane >> 2);
        #pragma unroll
        for (int nt = 0; nt < 4; nt++) {
            const int col = bn + wn * 32 + nt * 8 + (lane & 3) * 2;
            const float bx = bias[col], by = bias[col + 1];
            float2 v0 = { acc[mt][nt][0] + bx, acc[mt][nt][1] + by };
            float2 v1 = { acc[mt][nt][2] + bx, acc[mt][nt][3] + by };
            *(float2*)&O[(size_t)r * 256 + col]       = v0;
            *(float2*)&O[(size_t)(r + 8) * 256 + col] = v1;
        }
    }
}

// ---------------- conversion / precompute kernels ----------------
__global__ __launch_bounds__(256) void conv_in(
    const float* __restrict__ x, const float* __restrict__ rgb)
{
    const int s = blockIdx.y;
    const float* __restrict__ src = s ? rgb : x;
    const size_t m = blockIdx.x;
    const int k = threadIdx.x;
    float v = src[m * 256 + k];
    __half hi = __float2half_rn(v);
    __half lo = __float2half_rn(v - __half2float(hi));
    g_A[s][m * KSP + k] = hi;
    g_A[s][m * KSP + 256 + k] = lo;
}

__global__ __launch_bounds__(256) void conv_w(
    const float* __restrict__ w_qkv, const float* __restrict__ w_qkv_rgb,
    const float* __restrict__ w_proj, const float* __restrict__ w_proj_rgb)
{
    const int which = blockIdx.y;
    const float* src; __half* dst; int NC;
    switch (which) {
        case 0: src = w_qkv;       dst = g_Wqkv[0];  NC = 768; break;
        case 1: src = w_qkv_rgb;   dst = g_Wqkv[1];  NC = 768; break;
        case 2: src = w_proj;      dst = g_Wproj[0]; NC = 256; break;
        default: src = w_proj_rgb; dst = g_Wproj[1]; NC = 256; break;
    }
    int idx = blockIdx.x * 256 + threadIdx.x;
    if (idx >= 256 * NC) return;
    int k = idx / NC, n = idx % NC;
    dst[(size_t)n * 256 + k] = __float2half_rn(src[idx]);
}

__global__ __launch_bounds__(256) void prep_bm(
    const float* __restrict__ mask, const float* __restrict__ bias_table,
    const int* __restrict__ rel_idx)
{
    const int w = blockIdx.x, h = blockIdx.y;
    float* __restrict__ dst = g_bm + (size_t)(w * H_ + h) * NN2;
    const float* __restrict__ msk = mask + (size_t)w * NN2;
    for (int idx = threadIdx.x; idx < NN2; idx += 256)
        dst[idx] = bias_table[rel_idx[idx] * H_ + h] + msk[idx];
}

// ---------------- fused attention (fp32, register-blocked) ----------------
__global__ __launch_bounds__(192) void attn_kernel()
{
    const int b = blockIdx.x, h = blockIdx.y, p = blockIdx.z;
    const int qs = p ^ 1, kv = p;
    const float* __restrict__ qb = g_lin[qs] + (size_t)b * N_ * 768 + h * 32;
    const float* __restrict__ kb = g_lin[kv] + (size_t)b * N_ * 768 + 256 + h * 32;
    const float* __restrict__ vb = g_lin[kv] + (size_t)b * N_ * 768 + 512 + h * 32;
    const float* __restrict__ bm = g_bm + (size_t)((b & (NW_ - 1)) * H_ + h) * NN2;

    __shared__ float qT[32 * 56];   // [d][n]
    __shared__ float kT[32 * 56];   // [d][n]; reused as PV partial buffer (1768 floats)
    __shared__ float V[N_ * 36];    // [n][d]
    __shared__ float S[52 * 56];    // padded: PV tile reads rows 49-51

    const int tid = threadIdx.x;
    for (int i = tid; i < N_ * 32; i += 192) {
        int n = i >> 5, d = i & 31;
        qT[d * 56 + n] = qb[n * 768 + d];
        kT[d * 56 + n] = kb[n * 768 + d];
        V[n * 36 + d]  = vb[n * 768 + d];
    }
    for (int i = tid; i < 3 * 56; i += 192) S[49 * 56 + i] = 0.f;
    __syncthreads();

    // QK^T + combined bias/mask: 13x13 grid of 4x4 tiles
    if (tid < 169) {
        const int it = tid / 13, jt = tid - (tid / 13) * 13;
        const int i0 = it * 4, j0 = jt * 4;
        float acc[4][4] = {};
        #pragma unroll
        for (int d = 0; d < 32; d++) {
            float4 a  = *(const float4*)&qT[d * 56 + i0];
            float4 bb = *(const float4*)&kT[d * 56 + j0];
            float ar[4] = {a.x, a.y, a.z, a.w};
            float br[4] = {bb.x, bb.y, bb.z, bb.w};
            #pragma unroll
            for (int r = 0; r < 4; r++)
                #pragma unroll
                for (int c = 0; c < 4; c++)
                    acc[r][c] += ar[r] * br[c];
        }
        #pragma unroll
        for (int r = 0; r < 4; r++) {
            int i = i0 + r;
            if (i >= N_) break;
            #pragma unroll
            for (int c = 0; c < 4; c++) {
                int j = j0 + c;
                if (j >= N_) continue;
                S[i * 56 + j] = acc[r][c] + bm[i * N_ + j];
            }
        }
    }
    __syncthreads();

    // softmax: 6 warps stride rows
    {
        const int w = tid >> 5, lane = tid & 31;
        for (int r = w; r < N_; r += 6) {
            float* row = &S[r * 56];
            float v1 = row[lane];
            float v2 = (lane + 32 < N_) ? row[lane + 32] : -1e30f;
            float mx = fmaxf(v1, v2);
            #pragma unroll
            for (int o = 16; o; o >>= 1) mx = fmaxf(mx, __shfl_xor_sync(~0u, mx, o));
            float e1 = __expf(v1 - mx);
            float e2 = (lane + 32 < N_) ? __expf(v2 - mx) : 0.f;
            float s = e1 + e2;
            #pragma unroll
            for (int o = 16; o; o >>= 1) s += __shfl_xor_sync(~0u, s, o);
            float inv = 1.f / s;
            row[lane] = e1 * inv;
            if (lane + 32 < N_) row[lane + 32] = e2 * inv;
        }
    }
    __syncthreads();

    // PV: 13(i) x 8(d) grid of 4x4 tiles, j split in two halves -> 208 items.
    // half=0: j in [0,25), half=1: j in [25,49). half1 partials via smem (over kT).
    float* Pbuf = kT;   // 104 tiles * stride 17 = 1768 floats <= 1792
    float oAcc[2][4][4];

    #pragma unroll
    for (int rnd = 0; rnd < 2; rnd++) {
        const int t = tid + rnd * 192;
        if (t < 208) {
            const int pairIdx = t >> 1, half = t & 1;
            const int i0 = (pairIdx >> 3) * 4, d0 = (pairIdx & 7) * 4;
            float o[4][4] = {};
            const int jb = half ? 25 : 0, je = half ? 49 : 25;
            for (int j = jb; j < je; j++) {
                float4 vv = *(const float4*)&V[j * 36 + d0];
                float vr[4] = {vv.x, vv.y, vv.z, vv.w};
                #pragma unroll
                for (int r = 0; r < 4; r++) {
                    float pr = S[(i0 + r) * 56 + j];
                    #pragma unroll
                    for (int c = 0; c < 4; c++) o[r][c] += pr * vr[c];
                }
            }
            #pragma unroll
            for (int r = 0; r < 4; r++)
                #pragma unroll
                for (int c = 0; c < 4; c++) oAcc[rnd][r][c] = o[r][c];
        }
    }
    __syncthreads();     // all PV reads of S done; kT (QK) long dead

    // half1 writes partials
    #pragma unroll
    for (int rnd = 0; rnd < 2; rnd++) {
        const int t = tid + rnd * 192;
        if (t < 208 && (t & 1)) {
            float* Pp = &Pbuf[(t >> 1) * 17];
            #pragma unroll
            for (int r = 0; r < 4; r++)
                #pragma unroll
                for (int c = 0; c < 4; c++) Pp[r * 4 + c] = oAcc[rnd][r][c];
        }
    }
    __syncthreads();

    // half0 reduces + stores
    #pragma unroll
    for (int rnd = 0; rnd < 2; rnd++) {
        const int t = tid + rnd * 192;
        if (t < 208 && !(t & 1)) {
            const int pairIdx = t >> 1;
            const int i0 = (pairIdx >> 3) * 4, d0 = (pairIdx & 7) * 4;
            const float* Pp = &Pbuf[pairIdx * 17];
            #pragma unroll
            for (int r = 0; r < 4; r++) {
                int i = i0 + r;
                if (i >= N_) break;
                __half* dst = &g_aob[p][((size_t)b * N_ + i) * KSP + h * 32 + d0];
                float f[4];
                #pragma unroll
                for (int c = 0; c < 4; c++) f[c] = oAcc[rnd][r][c] + Pp[r * 4 + c];
                __half hh[4], ll[4];
                #pragma unroll
                for (int c = 0; c < 4; c++) {
                    hh[c] = __float2half_rn(f[c]);
                    ll[c] = __float2half_rn(f[c] - __half2float(hh[c]));
                }
                *(__half2*)(dst)           = __halves2half2(hh[0], hh[1]);
                *(__half2*)(dst + 2)       = __halves2half2(hh[2], hh[3]);
                *(__half2*)(dst + 256)     = __halves2half2(ll[0], ll[1]);
                *(__half2*)(dst + 258)     = __halves2half2(ll[2], ll[3]);
            }
        }
    }
}

// ---------------- host launcher ----------------
extern "C" void kernel_launch(void* const* d_in, const int* in_sizes, int n_in,
                              void* d_out, int out_size)
{
    const float* x          = (const float*)d_in[0];
    const float* rgb        = (const float*)d_in[1];
    const float* mask       = (const float*)d_in[2];
    const float* w_qkv      = (const float*)d_in[3];
    const float* b_qkv      = (const float*)d_in[4];
    const float* w_qkv_rgb  = (const float*)d_in[5];
    const float* b_qkv_rgb  = (const float*)d_in[6];
    const float* bias_table = (const float*)d_in[7];
    const float* w_proj     = (const float*)d_in[8];
    const float* b_proj     = (const float*)d_in[9];
    const float* w_proj_rgb = (const float*)d_in[10];
    const float* b_proj_rgb = (const float*)d_in[11];
    const int*   rel_idx    = (const int*)d_in[12];
    float* out = (float*)d_out;

    cudaFuncSetAttribute(qkv_hmma,  cudaFuncAttributeMaxDynamicSharedMemorySize, SMEM_SZ);
    cudaFuncSetAttribute(proj_hmma, cudaFuncAttributeMaxDynamicSharedMemorySize, SMEM_SZ);

    conv_w<<<dim3(768, 4), 256>>>(w_qkv, w_qkv_rgb, w_proj, w_proj_rgb);
    prep_bm<<<dim3(NW_, H_), 256>>>(mask, bias_table, rel_idx);
    conv_in<<<dim3(MT, 2), 256>>>(x, rgb);

    qkv_hmma<<<dim3(768 / BN, MT / BM, 2), 256, SMEM_SZ>>>(b_qkv, b_qkv_rgb);

    attn_kernel<<<dim3(B_, H_, 2), 192>>>();

    proj_hmma<<<dim3(256 / BN, MT / BM, 2), 256, SMEM_SZ>>>(b_proj, b_proj_rgb, out);
}

// round 11
// speedup vs baseline: 1.1475x; 1.1475x over previous
#include <cuda_runtime.h>
#include <cuda_fp16.h>
#include <cstdint>

#define B_  4096
#define N_  49
#define H_  8
#define NW_ 64
#define MT  (B_ * N_)              // 200704 rows
#define KSP 512                    // 2-term split K for QKV (2 * 256)
#define SZ_AO ((size_t)MT * 256)
#define NN2 (N_ * N_)              // 2401

#define SCALE_F 0.17677669529663687f

// ---------------- scratch (device globals; no runtime alloc) ----------------
__device__ __half g_A[2][(size_t)MT * KSP];     // input split [hi, lo] fp16
__device__ __half g_Wqkv[2][768 * 256];         // Wt[n][k] fp16
__device__ __half g_Wproj[2][256 * 256];
__device__ float  g_lin[2][(size_t)MT * 768];   // qkv linear out (q|k|v)
__device__ __half g_aob[2][(size_t)MT * 256];   // attn out, fp16 (hi only)
__device__ float  g_bm[NW_ * H_ * NN2];         // combined bias+mask

// ---------------- GEMM config (R7 proven config) ----------------
#define BM 128
#define BN 128
#define SA_STR 40
#define SB_STR 264

struct GSmem {
    __align__(16) __half B[BN * SB_STR];
    __align__(16) __half A[4][BM * SA_STR];
};
#define SMEM_SZ ((int)sizeof(GSmem))

__device__ __forceinline__ void cp16(uint32_t dst, const void* src) {
    asm volatile("cp.async.cg.shared.global [%0], [%1], 16;" :: "r"(dst), "l"(src));
}
__device__ __forceinline__ void cp_commit() {
    asm volatile("cp.async.commit_group;" ::: "memory");
}
template<int NN> __device__ __forceinline__ void cp_wait() {
    asm volatile("cp.async.wait_group %0;" :: "n"(NN) : "memory");
}

__device__ __forceinline__ void mma16816(float* d, const uint32_t* a, const uint32_t* b) {
    asm volatile(
        "mma.sync.aligned.m16n8k16.row.col.f32.f16.f16.f32 "
        "{%0,%1,%2,%3}, {%4,%5,%6,%7}, {%8,%9}, {%0,%1,%2,%3};"
        : "+f"(d[0]), "+f"(d[1]), "+f"(d[2]), "+f"(d[3])
        : "r"(a[0]), "r"(a[1]), "r"(a[2]), "r"(a[3]), "r"(b[0]), "r"(b[1]));
}

#define LDSM_X4(r, addr)                                                     \
    asm volatile("ldmatrix.sync.aligned.m8n8.x4.shared.b16 {%0,%1,%2,%3}, [%4];" \
        : "=r"((r)[0]), "=r"((r)[1]), "=r"((r)[2]), "=r"((r)[3]) : "r"(addr))

// GEMM mainloop, templated on the A K-dimension (chunks of 32).
template<int KD>
__device__ __forceinline__ void gemm_main(
    GSmem& sm, const __half* __restrict__ A, const __half* __restrict__ W,
    int bm, int bn, float acc[4][4][4])
{
    constexpr int NCH = KD / 32;
    const int tid = threadIdx.x;
    const uint32_t sB = (uint32_t)__cvta_generic_to_shared(sm.B);
    const uint32_t sA = (uint32_t)__cvta_generic_to_shared(sm.A);

    #pragma unroll
    for (int i = 0; i < 16; i++) {
        int idx = tid + i * 256;
        int r = idx >> 5, g = idx & 31;
        cp16(sB + (uint32_t)(r * SB_STR + g * 8) * 2,
             W + (size_t)(bn + r) * 256 + g * 8);
    }
    cp_commit();

    auto issueA = [&](int c) {
        uint32_t dst = sA + (uint32_t)((c & 3) * BM * SA_STR) * 2;
        #pragma unroll
        for (int i = 0; i < 2; i++) {
            int idx = tid + i * 256;
            int r = idx >> 2, g = idx & 3;
            cp16(dst + (uint32_t)(r * SA_STR + g * 8) * 2,
                 A + (size_t)(bm + r) * KD + c * 32 + g * 8);
        }
        cp_commit();
    };
    issueA(0); issueA(1); issueA(2);

    const int lane = tid & 31;
    const int wm = (tid >> 5) & 1, wn = tid >> 6;

    const int a_row = wm * 64 + (lane & 7) + ((lane >> 3) & 1) * 8;
    const int a_col = (lane >> 4) * 8;
    const int b_row = wn * 32 + (lane >> 4) * 8 + (lane & 7);
    const int b_col = ((lane >> 3) & 1) * 8;

    auto compute = [&](int c) {
        const uint32_t aBase = sA + (uint32_t)((c & 3) * BM * SA_STR) * 2;
        const uint32_t bBase = sB + (uint32_t)((c & 7) * 32) * 2;
        #pragma unroll
        for (int ks = 0; ks < 2; ks++) {
            const int kb = ks * 16;
            uint32_t af[4][4], bf[2][4];
            #pragma unroll
            for (int mt = 0; mt < 4; mt++)
                LDSM_X4(af[mt],
                        aBase + (uint32_t)((a_row + mt * 16) * SA_STR + kb + a_col) * 2);
            #pragma unroll
            for (int pr = 0; pr < 2; pr++)
                LDSM_X4(bf[pr],
                        bBase + (uint32_t)((b_row + pr * 16) * SB_STR + kb + b_col) * 2);
            #pragma unroll
            for (int mt = 0; mt < 4; mt++)
                #pragma unroll
                for (int nt = 0; nt < 4; nt++)
                    mma16816(acc[mt][nt], af[mt], &bf[nt >> 1][(nt & 1) * 2]);
        }
    };

    for (int c = 0; c < NCH - 3; c++) {
        cp_wait<2>();
        __syncthreads();
        issueA(c + 3);
        compute(c);
    }
    cp_wait<2>(); __syncthreads(); compute(NCH - 3);
    cp_wait<1>(); __syncthreads(); compute(NCH - 2);
    cp_wait<0>(); __syncthreads(); compute(NCH - 1);
}

// ---------------- GEMM kernels ----------------
__global__ __launch_bounds__(256, 2) void qkv_hmma(
    const float* __restrict__ b0, const float* __restrict__ b1)
{
    extern __shared__ char smem_raw[];
    GSmem& sm = *(GSmem*)smem_raw;
    const int stream = blockIdx.z;
    const int bn = blockIdx.x * BN;
    const int bm = blockIdx.y * BM;

    float acc[4][4][4] = {};
    gemm_main<KSP>(sm, g_A[stream], g_Wqkv[stream], bm, bn, acc);

    const float* __restrict__ bias = stream ? b1 : b0;
    float* __restrict__ O = g_lin[stream];
    const int lane = threadIdx.x & 31;
    const int wm = (threadIdx.x >> 5) & 1, wn = threadIdx.x >> 6;
    const float sc = (bn < 256) ? SCALE_F : 1.0f;

    #pragma unroll
    for (int mt = 0; mt < 4; mt++) {
        const int r = bm + wm * 64 + mt * 16 + (lane >> 2);
        #pragma unroll
        for (int nt = 0; nt < 4; nt++) {
            const int col = bn + wn * 32 + nt * 8 + (lane & 3) * 2;
            const float bx = bias[col], by = bias[col + 1];
            float2 v0 = { (acc[mt][nt][0] + bx) * sc, (acc[mt][nt][1] + by) * sc };
            float2 v1 = { (acc[mt][nt][2] + bx) * sc, (acc[mt][nt][3] + by) * sc };
            *(float2*)&O[(size_t)r * 768 + col]       = v0;
            *(float2*)&O[(size_t)(r + 8) * 768 + col] = v1;
        }
    }
}

__global__ __launch_bounds__(256, 2) void proj_hmma(
    const float* __restrict__ bp0, const float* __restrict__ bp1,
    float* __restrict__ out)
{
    extern __shared__ char smem_raw[];
    GSmem& sm = *(GSmem*)smem_raw;
    const int p = blockIdx.z;
    const int bn = blockIdx.x * BN;
    const int bm = blockIdx.y * BM;

    float acc[4][4][4] = {};
    gemm_main<256>(sm, g_aob[p], g_Wproj[p], bm, bn, acc);

    const float* __restrict__ bias = p ? bp1 : bp0;
    float* __restrict__ O = out + (size_t)p * SZ_AO;
    const int lane = threadIdx.x & 31;
    const int wm = (threadIdx.x >> 5) & 1, wn = threadIdx.x >> 6;

    #pragma unroll
    for (int mt = 0; mt < 4; mt++) {
        const int r = bm + wm * 64 + mt * 16 + (lane >> 2);
        #pragma unroll
        for (int nt = 0; nt < 4; nt++) {
            const int col = bn + wn * 32 + nt * 8 + (lane & 3) * 2;
            const float bx = bias[col], by = bias[col + 1];
            float2 v0 = { acc[mt][nt][0] + bx, acc[mt][nt][1] + by };
            float2 v1 = { acc[mt][nt][2] + bx, acc[mt][nt][3] + by };
            *(float2*)&O[(size_t)r * 256 + col]       = v0;
            *(float2*)&O[(size_t)(r + 8) * 256 + col] = v1;
        }
    }
}

// ---------------- conversion / precompute kernels ----------------
__global__ __launch_bounds__(256) void conv_in(
    const float* __restrict__ x, const float* __restrict__ rgb)
{
    const int s = blockIdx.y;
    const float* __restrict__ src = s ? rgb : x;
    const size_t m = blockIdx.x;
    const int k = threadIdx.x;
    float v = src[m * 256 + k];
    __half hi = __float2half_rn(v);
    __half lo = __float2half_rn(v - __half2float(hi));
    g_A[s][m * KSP + k] = hi;
    g_A[s][m * KSP + 256 + k] = lo;
}

__global__ __launch_bounds__(256) void conv_w(
    const float* __restrict__ w_qkv, const float* __restrict__ w_qkv_rgb,
    const float* __restrict__ w_proj, const float* __restrict__ w_proj_rgb)
{
    const int which = blockIdx.y;
    const float* src; __half* dst; int NC;
    switch (which) {
        case 0: src = w_qkv;       dst = g_Wqkv[0];  NC = 768; break;
        case 1: src = w_qkv_rgb;   dst = g_Wqkv[1];  NC = 768; break;
        case 2: src = w_proj;      dst = g_Wproj[0]; NC = 256; break;
        default: src = w_proj_rgb; dst = g_Wproj[1]; NC = 256; break;
    }
    int idx = blockIdx.x * 256 + threadIdx.x;
    if (idx >= 256 * NC) return;
    int k = idx / NC, n = idx % NC;
    dst[(size_t)n * 256 + k] = __float2half_rn(src[idx]);
}

__global__ __launch_bounds__(256) void prep_bm(
    const float* __restrict__ mask, const float* __restrict__ bias_table,
    const int* __restrict__ rel_idx)
{
    const int w = blockIdx.x, h = blockIdx.y;
    float* __restrict__ dst = g_bm + (size_t)(w * H_ + h) * NN2;
    const float* __restrict__ msk = mask + (size_t)w * NN2;
    for (int idx = threadIdx.x; idx < NN2; idx += 256)
        dst[idx] = bias_table[rel_idx[idx] * H_ + h] + msk[idx];
}

// ---------------- fused attention (fp32, register-blocked; R7 version) ------
__global__ __launch_bounds__(192) void attn_kernel()
{
    const int b = blockIdx.x, h = blockIdx.y, p = blockIdx.z;
    const int qs = p ^ 1, kv = p;
    const float* __restrict__ qb = g_lin[qs] + (size_t)b * N_ * 768 + h * 32;
    const float* __restrict__ kb = g_lin[kv] + (size_t)b * N_ * 768 + 256 + h * 32;
    const float* __restrict__ vb = g_lin[kv] + (size_t)b * N_ * 768 + 512 + h * 32;
    const float* __restrict__ bm = g_bm + (size_t)((b & (NW_ - 1)) * H_ + h) * NN2;

    __shared__ float qT[32 * 56];   // [d][n]
    __shared__ float kT[32 * 56];
    __shared__ float V[N_ * 36];    // [n][d]
    __shared__ float S[52 * 56];    // padded: PV tile reads rows 49-51

    const int tid = threadIdx.x;
    for (int i = tid; i < N_ * 32; i += 192) {
        int n = i >> 5, d = i & 31;
        qT[d * 56 + n] = qb[n * 768 + d];
        kT[d * 56 + n] = kb[n * 768 + d];
        V[n * 36 + d]  = vb[n * 768 + d];
    }
    for (int i = tid; i < 3 * 56; i += 192) S[49 * 56 + i] = 0.f;
    __syncthreads();

    if (tid < 169) {
        const int it = tid / 13, jt = tid - (tid / 13) * 13;
        const int i0 = it * 4, j0 = jt * 4;
        float acc[4][4] = {};
        #pragma unroll
        for (int d = 0; d < 32; d++) {
            float4 a  = *(const float4*)&qT[d * 56 + i0];
            float4 bb = *(const float4*)&kT[d * 56 + j0];
            float ar[4] = {a.x, a.y, a.z, a.w};
            float br[4] = {bb.x, bb.y, bb.z, bb.w};
            #pragma unroll
            for (int r = 0; r < 4; r++)
                #pragma unroll
                for (int c = 0; c < 4; c++)
                    acc[r][c] += ar[r] * br[c];
        }
        #pragma unroll
        for (int r = 0; r < 4; r++) {
            int i = i0 + r;
            if (i >= N_) break;
            #pragma unroll
            for (int c = 0; c < 4; c++) {
                int j = j0 + c;
                if (j >= N_) continue;
                S[i * 56 + j] = acc[r][c] + bm[i * N_ + j];
            }
        }
    }
    __syncthreads();

    {
        const int w = tid >> 5, lane = tid & 31;
        for (int r = w; r < N_; r += 6) {
            float* row = &S[r * 56];
            float v1 = row[lane];
            float v2 = (lane + 32 < N_) ? row[lane + 32] : -1e30f;
            float mx = fmaxf(v1, v2);
            #pragma unroll
            for (int o = 16; o; o >>= 1) mx = fmaxf(mx, __shfl_xor_sync(~0u, mx, o));
            float e1 = __expf(v1 - mx);
            float e2 = (lane + 32 < N_) ? __expf(v2 - mx) : 0.f;
            float s = e1 + e2;
            #pragma unroll
            for (int o = 16; o; o >>= 1) s += __shfl_xor_sync(~0u, s, o);
            float inv = 1.f / s;
            row[lane] = e1 * inv;
            if (lane + 32 < N_) row[lane + 32] = e2 * inv;
        }
    }
    __syncthreads();

    // PV: 13(i) x 16(d) grid of 4x2 tiles = 208 over 192 threads
    for (int t = tid; t < 208; t += 192) {
        const int it = t >> 4, dt = t & 15;
        const int i0 = it * 4, d0 = dt * 2;
        float o[4][2] = {};
        for (int j = 0; j < N_; j++) {
            float2 vv = *(const float2*)&V[j * 36 + d0];
            #pragma unroll
            for (int r = 0; r < 4; r++) {
                float pr = S[(i0 + r) * 56 + j];
                o[r][0] += pr * vv.x;
                o[r][1] += pr * vv.y;
            }
        }
        #pragma unroll
        for (int r = 0; r < 4; r++) {
            int i = i0 + r;
            if (i >= N_) break;
            __half* dst = &g_aob[p][((size_t)b * N_ + i) * 256 + h * 32 + d0];
            *(__half2*)dst = __halves2half2(__float2half_rn(o[r][0]),
                                            __float2half_rn(o[r][1]));
        }
    }
}

// ---------------- host launcher ----------------
extern "C" void kernel_launch(void* const* d_in, const int* in_sizes, int n_in,
                              void* d_out, int out_size)
{
    const float* x          = (const float*)d_in[0];
    const float* rgb        = (const float*)d_in[1];
    const float* mask       = (const float*)d_in[2];
    const float* w_qkv      = (const float*)d_in[3];
    const float* b_qkv      = (const float*)d_in[4];
    const float* w_qkv_rgb  = (const float*)d_in[5];
    const float* b_qkv_rgb  = (const float*)d_in[6];
    const float* bias_table = (const float*)d_in[7];
    const float* w_proj     = (const float*)d_in[8];
    const float* b_proj     = (const float*)d_in[9];
    const float* w_proj_rgb = (const float*)d_in[10];
    const float* b_proj_rgb = (const float*)d_in[11];
    const int*   rel_idx    = (const int*)d_in[12];
    float* out = (float*)d_out;

    cudaFuncSetAttribute(qkv_hmma,  cudaFuncAttributeMaxDynamicSharedMemorySize, SMEM_SZ);
    cudaFuncSetAttribute(proj_hmma, cudaFuncAttributeMaxDynamicSharedMemorySize, SMEM_SZ);

    conv_w<<<dim3(768, 4), 256>>>(w_qkv, w_qkv_rgb, w_proj, w_proj_rgb);
    prep_bm<<<dim3(NW_, H_), 256>>>(mask, bias_table, rel_idx);
    conv_in<<<dim3(MT, 2), 256>>>(x, rgb);

    qkv_hmma<<<dim3(768 / BN, MT / BM, 2), 256, SMEM_SZ>>>(b_qkv, b_qkv_rgb);

    attn_kernel<<<dim3(B_, H_, 2), 192>>>();

    proj_hmma<<<dim3(256 / BN, MT / BM, 2), 256, SMEM_SZ>>>(b_proj, b_proj_rgb, out);
}

// round 13
// speedup vs baseline: 1.7376x; 1.5143x over previous
#include <cuda_runtime.h>
#include <cuda_fp16.h>
#include <cstdint>

#define B_  4096
#define N_  49
#define H_  8
#define NW_ 64
#define MT  (B_ * N_)              // 200704 rows
#define KSP 512                    // 2-term split K for QKV (2 * 256)
#define SZ_AO ((size_t)MT * 256)
#define NN2 (N_ * N_)              // 2401

#define SCALE_F 0.17677669529663687f

// ---------------- scratch (device globals; no runtime alloc) ----------------
__device__ __half g_A[2][(size_t)MT * KSP];     // input split [hi, lo] fp16
__device__ __half g_Wqkv[2][768 * 256];         // Wt[n][k] fp16
__device__ __half g_Wproj[2][256 * 256];
__device__ float  g_lin[2][(size_t)MT * 768];   // qkv linear out (q|k|v)
__device__ __half g_aob[2][(size_t)MT * 256];   // attn out, fp16 (hi only)
__device__ float  g_bm[NW_ * H_ * NN2];         // combined bias+mask

// ---------------- GEMM config (R7/R11 proven config) ----------------
#define BM 128
#define BN 128
#define SA_STR 40
#define SB_STR 264

struct GSmem {
    __align__(16) __half B[BN * SB_STR];
    __align__(16) __half A[4][BM * SA_STR];
};
#define SMEM_SZ ((int)sizeof(GSmem))

__device__ __forceinline__ void cp16(uint32_t dst, const void* src) {
    asm volatile("cp.async.cg.shared.global [%0], [%1], 16;" :: "r"(dst), "l"(src));
}
__device__ __forceinline__ void cp_commit() {
    asm volatile("cp.async.commit_group;" ::: "memory");
}
template<int NN> __device__ __forceinline__ void cp_wait() {
    asm volatile("cp.async.wait_group %0;" :: "n"(NN) : "memory");
}

__device__ __forceinline__ void mma16816(float* d, const uint32_t* a, const uint32_t* b) {
    asm volatile(
        "mma.sync.aligned.m16n8k16.row.col.f32.f16.f16.f32 "
        "{%0,%1,%2,%3}, {%4,%5,%6,%7}, {%8,%9}, {%0,%1,%2,%3};"
        : "+f"(d[0]), "+f"(d[1]), "+f"(d[2]), "+f"(d[3])
        : "r"(a[0]), "r"(a[1]), "r"(a[2]), "r"(a[3]), "r"(b[0]), "r"(b[1]));
}

#define LDSM_X4(r, addr)                                                     \
    asm volatile("ldmatrix.sync.aligned.m8n8.x4.shared.b16 {%0,%1,%2,%3}, [%4];" \
        : "=r"((r)[0]), "=r"((r)[1]), "=r"((r)[2]), "=r"((r)[3]) : "r"(addr))

#define LDSM_X4_T(r, addr)                                                   \
    asm volatile("ldmatrix.sync.aligned.m8n8.x4.trans.shared.b16 {%0,%1,%2,%3}, [%4];" \
        : "=r"((r)[0]), "=r"((r)[1]), "=r"((r)[2]), "=r"((r)[3]) : "r"(addr))

// GEMM mainloop, templated on the A K-dimension (chunks of 32).
template<int KD>
__device__ __forceinline__ void gemm_main(
    GSmem& sm, const __half* __restrict__ A, const __half* __restrict__ W,
    int bm, int bn, float acc[4][4][4])
{
    constexpr int NCH = KD / 32;
    const int tid = threadIdx.x;
    const uint32_t sB = (uint32_t)__cvta_generic_to_shared(sm.B);
    const uint32_t sA = (uint32_t)__cvta_generic_to_shared(sm.A);

    #pragma unroll
    for (int i = 0; i < 16; i++) {
        int idx = tid + i * 256;
        int r = idx >> 5, g = idx & 31;
        cp16(sB + (uint32_t)(r * SB_STR + g * 8) * 2,
             W + (size_t)(bn + r) * 256 + g * 8);
    }
    cp_commit();

    auto issueA = [&](int c) {
        uint32_t dst = sA + (uint32_t)((c & 3) * BM * SA_STR) * 2;
        #pragma unroll
        for (int i = 0; i < 2; i++) {
            int idx = tid + i * 256;
            int r = idx >> 2, g = idx & 3;
            cp16(dst + (uint32_t)(r * SA_STR + g * 8) * 2,
                 A + (size_t)(bm + r) * KD + c * 32 + g * 8);
        }
        cp_commit();
    };
    issueA(0); issueA(1); issueA(2);

    const int lane = tid & 31;
    const int wm = (tid >> 5) & 1, wn = tid >> 6;

    const int a_row = wm * 64 + (lane & 7) + ((lane >> 3) & 1) * 8;
    const int a_col = (lane >> 4) * 8;
    const int b_row = wn * 32 + (lane >> 4) * 8 + (lane & 7);
    const int b_col = ((lane >> 3) & 1) * 8;

    auto compute = [&](int c) {
        const uint32_t aBase = sA + (uint32_t)((c & 3) * BM * SA_STR) * 2;
        const uint32_t bBase = sB + (uint32_t)((c & 7) * 32) * 2;
        #pragma unroll
        for (int ks = 0; ks < 2; ks++) {
            const int kb = ks * 16;
            uint32_t af[4][4], bf[2][4];
            #pragma unroll
            for (int mt = 0; mt < 4; mt++)
                LDSM_X4(af[mt],
                        aBase + (uint32_t)((a_row + mt * 16) * SA_STR + kb + a_col) * 2);
            #pragma unroll
            for (int pr = 0; pr < 2; pr++)
                LDSM_X4(bf[pr],
                        bBase + (uint32_t)((b_row + pr * 16) * SB_STR + kb + b_col) * 2);
            #pragma unroll
            for (int mt = 0; mt < 4; mt++)
                #pragma unroll
                for (int nt = 0; nt < 4; nt++)
                    mma16816(acc[mt][nt], af[mt], &bf[nt >> 1][(nt & 1) * 2]);
        }
    };

    for (int c = 0; c < NCH - 3; c++) {
        cp_wait<2>();
        __syncthreads();
        issueA(c + 3);
        compute(c);
    }
    cp_wait<2>(); __syncthreads(); compute(NCH - 3);
    cp_wait<1>(); __syncthreads(); compute(NCH - 2);
    cp_wait<0>(); __syncthreads(); compute(NCH - 1);
}

// ---------------- GEMM kernels ----------------
__global__ __launch_bounds__(256, 2) void qkv_hmma(
    const float* __restrict__ b0, const float* __restrict__ b1)
{
    extern __shared__ char smem_raw[];
    GSmem& sm = *(GSmem*)smem_raw;
    const int stream = blockIdx.z;
    const int bn = blockIdx.x * BN;
    const int bm = blockIdx.y * BM;

    float acc[4][4][4] = {};
    gemm_main<KSP>(sm, g_A[stream], g_Wqkv[stream], bm, bn, acc);

    const float* __restrict__ bias = stream ? b1 : b0;
    float* __restrict__ O = g_lin[stream];
    const int lane = threadIdx.x & 31;
    const int wm = (threadIdx.x >> 5) & 1, wn = threadIdx.x >> 6;
    const float sc = (bn < 256) ? SCALE_F : 1.0f;

    #pragma unroll
    for (int mt = 0; mt < 4; mt++) {
        const int r = bm + wm * 64 + mt * 16 + (lane >> 2);
        #pragma unroll
        for (int nt = 0; nt < 4; nt++) {
            const int col = bn + wn * 32 + nt * 8 + (lane & 3) * 2;
            const float bx = bias[col], by = bias[col + 1];
            float2 v0 = { (acc[mt][nt][0] + bx) * sc, (acc[mt][nt][1] + by) * sc };
            float2 v1 = { (acc[mt][nt][2] + bx) * sc, (acc[mt][nt][3] + by) * sc };
            *(float2*)&O[(size_t)r * 768 + col]       = v0;
            *(float2*)&O[(size_t)(r + 8) * 768 + col] = v1;
        }
    }
}

__global__ __launch_bounds__(256, 2) void proj_hmma(
    const float* __restrict__ bp0, const float* __restrict__ bp1,
    float* __restrict__ out)
{
    extern __shared__ char smem_raw[];
    GSmem& sm = *(GSmem*)smem_raw;
    const int p = blockIdx.z;
    const int bn = blockIdx.x * BN;
    const int bm = blockIdx.y * BM;

    float acc[4][4][4] = {};
    gemm_main<256>(sm, g_aob[p], g_Wproj[p], bm, bn, acc);

    const float* __restrict__ bias = p ? bp1 : bp0;
    float* __restrict__ O = out + (size_t)p * SZ_AO;
    const int lane = threadIdx.x & 31;
    const int wm = (threadIdx.x >> 5) & 1, wn = threadIdx.x >> 6;

    #pragma unroll
    for (int mt = 0; mt < 4; mt++) {
        const int r = bm + wm * 64 + mt * 16 + (lane >> 2);
        #pragma unroll
        for (int nt = 0; nt < 4; nt++) {
            const int col = bn + wn * 32 + nt * 8 + (lane & 3) * 2;
            const float bx = bias[col], by = bias[col + 1];
            float2 v0 = { acc[mt][nt][0] + bx, acc[mt][nt][1] + by };
            float2 v1 = { acc[mt][nt][2] + bx, acc[mt][nt][3] + by };
            *(float2*)&O[(size_t)r * 256 + col]       = v0;
            *(float2*)&O[(size_t)(r + 8) * 256 + col] = v1;
        }
    }
}

// ---------------- conversion / precompute kernels ----------------
__global__ __launch_bounds__(256) void conv_in(
    const float* __restrict__ x, const float* __restrict__ rgb)
{
    const int s = blockIdx.y;
    const float* __restrict__ src = s ? rgb : x;
    const size_t m = blockIdx.x;
    const int k = threadIdx.x;
    float v = src[m * 256 + k];
    __half hi = __float2half_rn(v);
    __half lo = __float2half_rn(v - __half2float(hi));
    g_A[s][m * KSP + k] = hi;
    g_A[s][m * KSP + 256 + k] = lo;
}

__global__ __launch_bounds__(256) void conv_w(
    const float* __restrict__ w_qkv, const float* __restrict__ w_qkv_rgb,
    const float* __restrict__ w_proj, const float* __restrict__ w_proj_rgb)
{
    const int which = blockIdx.y;
    const float* src; __half* dst; int NC;
    switch (which) {
        case 0: src = w_qkv;       dst = g_Wqkv[0];  NC = 768; break;
        case 1: src = w_qkv_rgb;   dst = g_Wqkv[1];  NC = 768; break;
        case 2: src = w_proj;      dst = g_Wproj[0]; NC = 256; break;
        default: src = w_proj_rgb; dst = g_Wproj[1]; NC = 256; break;
    }
    int idx = blockIdx.x * 256 + threadIdx.x;
    if (idx >= 256 * NC) return;
    int k = idx / NC, n = idx % NC;
    dst[(size_t)n * 256 + k] = __float2half_rn(src[idx]);
}

__global__ __launch_bounds__(256) void prep_bm(
    const float* __restrict__ mask, const float* __restrict__ bias_table,
    const int* __restrict__ rel_idx)
{
    const int w = blockIdx.x, h = blockIdx.y;
    float* __restrict__ dst = g_bm + (size_t)(w * H_ + h) * NN2;
    const float* __restrict__ msk = mask + (size_t)w * NN2;
    for (int idx = threadIdx.x; idx < NN2; idx += 256)
        dst[idx] = bias_table[rel_idx[idx] * H_ + h] + msk[idx];
}

// ---------------- fused attention (HMMA tensor-core version) ----------------
// One block per (b, h, p): 128 threads = 4 warps; warp w owns q-rows [16w,16w+16).
__global__ __launch_bounds__(128) void attn_kernel()
{
    const int b = blockIdx.x, h = blockIdx.y, p = blockIdx.z;
    const int qs = p ^ 1, kv = p;
    const float* __restrict__ qb = g_lin[qs] + (size_t)b * N_ * 768 + h * 32;
    const float* __restrict__ kb = g_lin[kv] + (size_t)b * N_ * 768 + 256 + h * 32;
    const float* __restrict__ vb = g_lin[kv] + (size_t)b * N_ * 768 + 512 + h * 32;
    const float* __restrict__ bm = g_bm + (size_t)((b & (NW_ - 1)) * H_ + h) * NN2;

    __shared__ __align__(16) __half Qs[64 * 40];
    __shared__ __align__(16) __half Ks[64 * 40];
    __shared__ __align__(16) __half Vs[64 * 40];
    __shared__ __align__(16) __half P [64 * 72];

    const int tid = threadIdx.x;

    // Load Q,K,V (49 rows x 32 d) fp32 -> fp16 smem
    for (int i = tid; i < N_ * 16; i += 128) {
        int n = i >> 4, dp = (i & 15) * 2;
        float2 q2 = *(const float2*)(qb + n * 768 + dp);
        float2 k2 = *(const float2*)(kb + n * 768 + dp);
        float2 v2 = *(const float2*)(vb + n * 768 + dp);
        *(__half2*)&Qs[n * 40 + dp] = __float22half2_rn(q2);
        *(__half2*)&Ks[n * 40 + dp] = __float22half2_rn(k2);
        *(__half2*)&Vs[n * 40 + dp] = __float22half2_rn(v2);
    }
    // Zero V pad rows 49..63 (NaN-proof)
    for (int i = tid; i < 15 * 40; i += 128)
        Vs[49 * 40 + i] = __ushort_as_half(0);
    // Zero P cols 56..63 for all 64 rows
    {
        int r = tid >> 1, c = (tid & 1) * 4;
        *(uint2*)&P[r * 72 + 56 + c] = make_uint2(0u, 0u);
    }
    __syncthreads();

    const int lane = tid & 31, w = tid >> 5;
    const uint32_t sQ = (uint32_t)__cvta_generic_to_shared(Qs);
    const uint32_t sK = (uint32_t)__cvta_generic_to_shared(Ks);
    const uint32_t sV = (uint32_t)__cvta_generic_to_shared(Vs);
    const uint32_t sP = (uint32_t)__cvta_generic_to_shared(P);

    // A-operand lane mapping (GEMM-proven)
    const int xr = (lane & 7) + ((lane >> 3) & 1) * 8;
    const int xc = (lane >> 4) * 8;
    // B-operand lane mapping (GEMM-proven: rows from lane&7 + (lane>>4)*8,
    // col half from (lane>>3)&1)
    const int kr = (lane >> 4) * 8 + (lane & 7);
    const int kc = ((lane >> 3) & 1) * 8;

    // ---- QK^T: 7 n-tiles x 2 k-steps per warp ----
    float acc[7][4] = {};
    #pragma unroll
    for (int ks = 0; ks < 2; ks++) {
        const int kb16 = ks * 16;
        uint32_t aq[4];
        LDSM_X4(aq, sQ + (uint32_t)((w * 16 + xr) * 40 + kb16 + xc) * 2);
        uint32_t bk[4][4];
        #pragma unroll
        for (int pr = 0; pr < 4; pr++)
            LDSM_X4(bk[pr], sK + (uint32_t)((pr * 16 + kr) * 40 + kb16 + kc) * 2);
        #pragma unroll
        for (int nt = 0; nt < 7; nt++)
            mma16816(acc[nt], aq, &bk[nt >> 1][(nt & 1) * 2]);
    }

    // ---- bias+mask add; mask cols >= 49 (assignment kills garbage/NaN) ----
    const int r0 = w * 16 + (lane >> 2);      // rows r0, r0+8
    const int c0 = (lane & 3) * 2;
    #pragma unroll
    for (int nt = 0; nt < 7; nt++) {
        const int col = nt * 8 + c0;
        #pragma unroll
        for (int e = 0; e < 4; e++) {
            const int rr = r0 + (e >> 1) * 8;
            const int cc = col + (e & 1);
            if (cc < N_) {
                if (rr < N_) acc[nt][e] += __ldg(&bm[rr * N_ + cc]);
            } else {
                acc[nt][e] = -1e30f;
            }
        }
    }

    // ---- softmax in registers (rows r0, r0+8; quad shuffles) ----
    float mx0 = -1e30f, mx1 = -1e30f;
    #pragma unroll
    for (int nt = 0; nt < 7; nt++) {
        mx0 = fmaxf(mx0, fmaxf(acc[nt][0], acc[nt][1]));
        mx1 = fmaxf(mx1, fmaxf(acc[nt][2], acc[nt][3]));
    }
    mx0 = fmaxf(mx0, __shfl_xor_sync(~0u, mx0, 1));
    mx0 = fmaxf(mx0, __shfl_xor_sync(~0u, mx0, 2));
    mx1 = fmaxf(mx1, __shfl_xor_sync(~0u, mx1, 1));
    mx1 = fmaxf(mx1, __shfl_xor_sync(~0u, mx1, 2));

    float s0 = 0.f, s1 = 0.f;
    #pragma unroll
    for (int nt = 0; nt < 7; nt++) {
        acc[nt][0] = __expf(acc[nt][0] - mx0);
        acc[nt][1] = __expf(acc[nt][1] - mx0);
        acc[nt][2] = __expf(acc[nt][2] - mx1);
        acc[nt][3] = __expf(acc[nt][3] - mx1);
        s0 += acc[nt][0] + acc[nt][1];
        s1 += acc[nt][2] + acc[nt][3];
    }
    s0 += __shfl_xor_sync(~0u, s0, 1);
    s0 += __shfl_xor_sync(~0u, s0, 2);
    s1 += __shfl_xor_sync(~0u, s1, 1);
    s1 += __shfl_xor_sync(~0u, s1, 2);
    const float inv0 = 1.f / s0, inv1 = 1.f / s1;

    // ---- write P (fp16) ----
    #pragma unroll
    for (int nt = 0; nt < 7; nt++) {
        const int col = nt * 8 + c0;
        *(__half2*)&P[r0 * 72 + col] =
            __halves2half2(__float2half_rn(acc[nt][0] * inv0),
                           __float2half_rn(acc[nt][1] * inv0));
        *(__half2*)&P[(r0 + 8) * 72 + col] =
            __halves2half2(__float2half_rn(acc[nt][2] * inv1),
                           __float2half_rn(acc[nt][3] * inv1));
    }
    __syncwarp();   // PV reads only this warp's P rows

    // ---- PV: K=64 (4 k-steps), 4 d-tiles; trans-ldmatrix on V is the
    //      B-operand (derived: lane l -> [d=l/4][j=(l&3)*2], matching spec) ----
    float o[4][4] = {};
    #pragma unroll
    for (int ks = 0; ks < 4; ks++) {
        uint32_t ap[4];
        LDSM_X4(ap, sP + (uint32_t)((w * 16 + xr) * 72 + ks * 16 + xc) * 2);
        uint32_t bv[2][4];
        #pragma unroll
        for (int pr = 0; pr < 2; pr++)
            LDSM_X4_T(bv[pr], sV + (uint32_t)((ks * 16 + xr) * 40 + pr * 16 + xc) * 2);
        #pragma unroll
        for (int nt = 0; nt < 4; nt++)
            mma16816(o[nt], ap, &bv[nt >> 1][(nt & 1) * 2]);
    }

    // ---- store output (fp16, guarded) ----
    __half* __restrict__ dstBase = &g_aob[p][((size_t)b * N_) * 256 + h * 32];
    #pragma unroll
    for (int nt = 0; nt < 4; nt++) {
        const int d = nt * 8 + c0;
        if (r0 < N_)
            *(__half2*)&dstBase[(size_t)r0 * 256 + d] =
                __halves2half2(__float2half_rn(o[nt][0]), __float2half_rn(o[nt][1]));
        if (r0 + 8 < N_)
            *(__half2*)&dstBase[(size_t)(r0 + 8) * 256 + d] =
                __halves2half2(__float2half_rn(o[nt][2]), __float2half_rn(o[nt][3]));
    }
}

// ---------------- host launcher ----------------
extern "C" void kernel_launch(void* const* d_in, const int* in_sizes, int n_in,
                              void* d_out, int out_size)
{
    const float* x          = (const float*)d_in[0];
    const float* rgb        = (const float*)d_in[1];
    const float* mask       = (const float*)d_in[2];
    const float* w_qkv      = (const float*)d_in[3];
    const float* b_qkv      = (const float*)d_in[4];
    const float* w_qkv_rgb  = (const float*)d_in[5];
    const float* b_qkv_rgb  = (const float*)d_in[6];
    const float* bias_table = (const float*)d_in[7];
    const float* w_proj     = (const float*)d_in[8];
    const float* b_proj     = (const float*)d_in[9];
    const float* w_proj_rgb = (const float*)d_in[10];
    const float* b_proj_rgb = (const float*)d_in[11];
    const int*   rel_idx    = (const int*)d_in[12];
    float* out = (float*)d_out;

    cudaFuncSetAttribute(qkv_hmma,  cudaFuncAttributeMaxDynamicSharedMemorySize, SMEM_SZ);
    cudaFuncSetAttribute(proj_hmma, cudaFuncAttributeMaxDynamicSharedMemorySize, SMEM_SZ);

    conv_w<<<dim3(768, 4), 256>>>(w_qkv, w_qkv_rgb, w_proj, w_proj_rgb);
    prep_bm<<<dim3(NW_, H_), 256>>>(mask, bias_table, rel_idx);
    conv_in<<<dim3(MT, 2), 256>>>(x, rgb);

    qkv_hmma<<<dim3(768 / BN, MT / BM, 2), 256, SMEM_SZ>>>(b_qkv, b_qkv_rgb);

    attn_kernel<<<dim3(B_, H_, 2), 128>>>();

    proj_hmma<<<dim3(256 / BN, MT / BM, 2), 256, SMEM_SZ>>>(b_proj, b_proj_rgb, out);
}

// round 14
// speedup vs baseline: 2.0875x; 1.2014x over previous
#include <cuda_runtime.h>
#include <cuda_fp16.h>
#include <cstdint>

#define B_  4096
#define N_  49
#define H_  8
#define NW_ 64
#define MT  (B_ * N_)              // 200704 rows
#define SZ_AO ((size_t)MT * 256)
#define NN2 (N_ * N_)              // 2401

#define SCALE_F 0.17677669529663687f

// ---------------- scratch (device globals; no runtime alloc) ----------------
__device__ __half g_A[2][(size_t)MT * 256];     // input fp16 (hi only)
__device__ __half g_Wqkv[2][768 * 256];         // Wt[n][k] fp16
__device__ __half g_Wproj[2][256 * 256];
__device__ __half g_lin[2][(size_t)MT * 768];   // qkv linear out fp16 (q|k|v)
__device__ __half g_aob[2][(size_t)MT * 256];   // attn out fp16
__device__ float  g_bm[NW_ * H_ * NN2];         // combined bias+mask

// ---------------- GEMM config (R7/R11 proven config) ----------------
#define BM 128
#define BN 128
#define SA_STR 40
#define SB_STR 264

struct GSmem {
    __align__(16) __half B[BN * SB_STR];
    __align__(16) __half A[4][BM * SA_STR];
};
#define SMEM_SZ ((int)sizeof(GSmem))

__device__ __forceinline__ void cp16(uint32_t dst, const void* src) {
    asm volatile("cp.async.cg.shared.global [%0], [%1], 16;" :: "r"(dst), "l"(src));
}
__device__ __forceinline__ void cp_commit() {
    asm volatile("cp.async.commit_group;" ::: "memory");
}
template<int NN> __device__ __forceinline__ void cp_wait() {
    asm volatile("cp.async.wait_group %0;" :: "n"(NN) : "memory");
}

__device__ __forceinline__ void mma16816(float* d, const uint32_t* a, const uint32_t* b) {
    asm volatile(
        "mma.sync.aligned.m16n8k16.row.col.f32.f16.f16.f32 "
        "{%0,%1,%2,%3}, {%4,%5,%6,%7}, {%8,%9}, {%0,%1,%2,%3};"
        : "+f"(d[0]), "+f"(d[1]), "+f"(d[2]), "+f"(d[3])
        : "r"(a[0]), "r"(a[1]), "r"(a[2]), "r"(a[3]), "r"(b[0]), "r"(b[1]));
}

#define LDSM_X4(r, addr)                                                     \
    asm volatile("ldmatrix.sync.aligned.m8n8.x4.shared.b16 {%0,%1,%2,%3}, [%4];" \
        : "=r"((r)[0]), "=r"((r)[1]), "=r"((r)[2]), "=r"((r)[3]) : "r"(addr))

#define LDSM_X4_T(r, addr)                                                   \
    asm volatile("ldmatrix.sync.aligned.m8n8.x4.trans.shared.b16 {%0,%1,%2,%3}, [%4];" \
        : "=r"((r)[0]), "=r"((r)[1]), "=r"((r)[2]), "=r"((r)[3]) : "r"(addr))

// GEMM mainloop, templated on the A K-dimension (chunks of 32).
template<int KD>
__device__ __forceinline__ void gemm_main(
    GSmem& sm, const __half* __restrict__ A, const __half* __restrict__ W,
    int bm, int bn, float acc[4][4][4])
{
    constexpr int NCH = KD / 32;
    const int tid = threadIdx.x;
    const uint32_t sB = (uint32_t)__cvta_generic_to_shared(sm.B);
    const uint32_t sA = (uint32_t)__cvta_generic_to_shared(sm.A);

    #pragma unroll
    for (int i = 0; i < 16; i++) {
        int idx = tid + i * 256;
        int r = idx >> 5, g = idx & 31;
        cp16(sB + (uint32_t)(r * SB_STR + g * 8) * 2,
             W + (size_t)(bn + r) * 256 + g * 8);
    }
    cp_commit();

    auto issueA = [&](int c) {
        uint32_t dst = sA + (uint32_t)((c & 3) * BM * SA_STR) * 2;
        #pragma unroll
        for (int i = 0; i < 2; i++) {
            int idx = tid + i * 256;
            int r = idx >> 2, g = idx & 3;
            cp16(dst + (uint32_t)(r * SA_STR + g * 8) * 2,
                 A + (size_t)(bm + r) * KD + c * 32 + g * 8);
        }
        cp_commit();
    };
    issueA(0); issueA(1); issueA(2);

    const int lane = tid & 31;
    const int wm = (tid >> 5) & 1, wn = tid >> 6;

    const int a_row = wm * 64 + (lane & 7) + ((lane >> 3) & 1) * 8;
    const int a_col = (lane >> 4) * 8;
    const int b_row = wn * 32 + (lane >> 4) * 8 + (lane & 7);
    const int b_col = ((lane >> 3) & 1) * 8;

    auto compute = [&](int c) {
        const uint32_t aBase = sA + (uint32_t)((c & 3) * BM * SA_STR) * 2;
        const uint32_t bBase = sB + (uint32_t)((c & 7) * 32) * 2;
        #pragma unroll
        for (int ks = 0; ks < 2; ks++) {
            const int kb = ks * 16;
            uint32_t af[4][4], bf[2][4];
            #pragma unroll
            for (int mt = 0; mt < 4; mt++)
                LDSM_X4(af[mt],
                        aBase + (uint32_t)((a_row + mt * 16) * SA_STR + kb + a_col) * 2);
            #pragma unroll
            for (int pr = 0; pr < 2; pr++)
                LDSM_X4(bf[pr],
                        bBase + (uint32_t)((b_row + pr * 16) * SB_STR + kb + b_col) * 2);
            #pragma unroll
            for (int mt = 0; mt < 4; mt++)
                #pragma unroll
                for (int nt = 0; nt < 4; nt++)
                    mma16816(acc[mt][nt], af[mt], &bf[nt >> 1][(nt & 1) * 2]);
        }
    };

    for (int c = 0; c < NCH - 3; c++) {
        cp_wait<2>();
        __syncthreads();
        issueA(c + 3);
        compute(c);
    }
    cp_wait<2>(); __syncthreads(); compute(NCH - 3);
    cp_wait<1>(); __syncthreads(); compute(NCH - 2);
    cp_wait<0>(); __syncthreads(); compute(NCH - 1);
}

// ---------------- GEMM kernels ----------------
__global__ __launch_bounds__(256, 2) void qkv_hmma(
    const float* __restrict__ b0, const float* __restrict__ b1)
{
    extern __shared__ char smem_raw[];
    GSmem& sm = *(GSmem*)smem_raw;
    const int stream = blockIdx.z;
    const int bn = blockIdx.x * BN;
    const int bm = blockIdx.y * BM;

    float acc[4][4][4] = {};
    gemm_main<256>(sm, g_A[stream], g_Wqkv[stream], bm, bn, acc);

    const float* __restrict__ bias = stream ? b1 : b0;
    __half* __restrict__ O = g_lin[stream];
    const int lane = threadIdx.x & 31;
    const int wm = (threadIdx.x >> 5) & 1, wn = threadIdx.x >> 6;
    const float sc = (bn < 256) ? SCALE_F : 1.0f;

    #pragma unroll
    for (int mt = 0; mt < 4; mt++) {
        const int r = bm + wm * 64 + mt * 16 + (lane >> 2);
        #pragma unroll
        for (int nt = 0; nt < 4; nt++) {
            const int col = bn + wn * 32 + nt * 8 + (lane & 3) * 2;
            const float bx = bias[col], by = bias[col + 1];
            *(__half2*)&O[(size_t)r * 768 + col] =
                __halves2half2(__float2half_rn((acc[mt][nt][0] + bx) * sc),
                               __float2half_rn((acc[mt][nt][1] + by) * sc));
            *(__half2*)&O[(size_t)(r + 8) * 768 + col] =
                __halves2half2(__float2half_rn((acc[mt][nt][2] + bx) * sc),
                               __float2half_rn((acc[mt][nt][3] + by) * sc));
        }
    }
}

__global__ __launch_bounds__(256, 2) void proj_hmma(
    const float* __restrict__ bp0, const float* __restrict__ bp1,
    float* __restrict__ out)
{
    extern __shared__ char smem_raw[];
    GSmem& sm = *(GSmem*)smem_raw;
    const int p = blockIdx.z;
    const int bn = blockIdx.x * BN;
    const int bm = blockIdx.y * BM;

    float acc[4][4][4] = {};
    gemm_main<256>(sm, g_aob[p], g_Wproj[p], bm, bn, acc);

    const float* __restrict__ bias = p ? bp1 : bp0;
    float* __restrict__ O = out + (size_t)p * SZ_AO;
    const int lane = threadIdx.x & 31;
    const int wm = (threadIdx.x >> 5) & 1, wn = threadIdx.x >> 6;

    #pragma unroll
    for (int mt = 0; mt < 4; mt++) {
        const int r = bm + wm * 64 + mt * 16 + (lane >> 2);
        #pragma unroll
        for (int nt = 0; nt < 4; nt++) {
            const int col = bn + wn * 32 + nt * 8 + (lane & 3) * 2;
            const float bx = bias[col], by = bias[col + 1];
            float2 v0 = { acc[mt][nt][0] + bx, acc[mt][nt][1] + by };
            float2 v1 = { acc[mt][nt][2] + bx, acc[mt][nt][3] + by };
            *(float2*)&O[(size_t)r * 256 + col]       = v0;
            *(float2*)&O[(size_t)(r + 8) * 256 + col] = v1;
        }
    }
}

// ---------------- conversion / precompute kernels ----------------
__global__ __launch_bounds__(256) void conv_in(
    const float* __restrict__ x, const float* __restrict__ rgb)
{
    const int s = blockIdx.y;
    const float* __restrict__ src = s ? rgb : x;
    size_t idx = (size_t)blockIdx.x * 256 + threadIdx.x;
    g_A[s][idx] = __float2half_rn(src[idx]);
}

__global__ __launch_bounds__(256) void conv_w(
    const float* __restrict__ w_qkv, const float* __restrict__ w_qkv_rgb,
    const float* __restrict__ w_proj, const float* __restrict__ w_proj_rgb)
{
    const int which = blockIdx.y;
    const float* src; __half* dst; int NC;
    switch (which) {
        case 0: src = w_qkv;       dst = g_Wqkv[0];  NC = 768; break;
        case 1: src = w_qkv_rgb;   dst = g_Wqkv[1];  NC = 768; break;
        case 2: src = w_proj;      dst = g_Wproj[0]; NC = 256; break;
        default: src = w_proj_rgb; dst = g_Wproj[1]; NC = 256; break;
    }
    int idx = blockIdx.x * 256 + threadIdx.x;
    if (idx >= 256 * NC) return;
    int k = idx / NC, n = idx % NC;
    dst[(size_t)n * 256 + k] = __float2half_rn(src[idx]);
}

__global__ __launch_bounds__(256) void prep_bm(
    const float* __restrict__ mask, const float* __restrict__ bias_table,
    const int* __restrict__ rel_idx)
{
    const int w = blockIdx.x, h = blockIdx.y;
    float* __restrict__ dst = g_bm + (size_t)(w * H_ + h) * NN2;
    const float* __restrict__ msk = mask + (size_t)w * NN2;
    for (int idx = threadIdx.x; idx < NN2; idx += 256)
        dst[idx] = bias_table[rel_idx[idx] * H_ + h] + msk[idx];
}

// ---------------- fused attention (HMMA tensor-core version) ----------------
// One block per (b, h, p): 128 threads = 4 warps; warp w owns q-rows [16w,16w+16).
__global__ __launch_bounds__(128) void attn_kernel()
{
    const int b = blockIdx.x, h = blockIdx.y, p = blockIdx.z;
    const int qs = p ^ 1, kv = p;
    const __half* __restrict__ qb = g_lin[qs] + (size_t)b * N_ * 768 + h * 32;
    const __half* __restrict__ kb = g_lin[kv] + (size_t)b * N_ * 768 + 256 + h * 32;
    const __half* __restrict__ vb = g_lin[kv] + (size_t)b * N_ * 768 + 512 + h * 32;
    const float* __restrict__ bm = g_bm + (size_t)((b & (NW_ - 1)) * H_ + h) * NN2;

    __shared__ __align__(16) __half Qs[64 * 40];
    __shared__ __align__(16) __half Ks[64 * 40];
    __shared__ __align__(16) __half Vs[64 * 40];
    __shared__ __align__(16) __half P [64 * 72];

    const int tid = threadIdx.x;

    // Load Q,K,V fp16 (49 rows x 32 d), uint2 = 4 halves per op
    for (int i = tid; i < N_ * 8; i += 128) {
        int n = i >> 3, dp = (i & 7) * 4;
        *(uint2*)&Qs[n * 40 + dp] = *(const uint2*)(qb + n * 768 + dp);
        *(uint2*)&Ks[n * 40 + dp] = *(const uint2*)(kb + n * 768 + dp);
        *(uint2*)&Vs[n * 40 + dp] = *(const uint2*)(vb + n * 768 + dp);
    }
    // Zero V pad rows 49..63 (NaN-proof)
    for (int i = tid; i < 15 * 40; i += 128)
        Vs[49 * 40 + i] = __ushort_as_half(0);
    // Zero P cols 56..63 for all 64 rows
    {
        int r = tid >> 1, c = (tid & 1) * 4;
        *(uint2*)&P[r * 72 + 56 + c] = make_uint2(0u, 0u);
    }
    __syncthreads();

    const int lane = tid & 31, w = tid >> 5;
    const uint32_t sQ = (uint32_t)__cvta_generic_to_shared(Qs);
    const uint32_t sK = (uint32_t)__cvta_generic_to_shared(Ks);
    const uint32_t sV = (uint32_t)__cvta_generic_to_shared(Vs);
    const uint32_t sP = (uint32_t)__cvta_generic_to_shared(P);

    // A-operand lane mapping (GEMM-proven)
    const int xr = (lane & 7) + ((lane >> 3) & 1) * 8;
    const int xc = (lane >> 4) * 8;
    // B-operand lane mapping (GEMM-proven)
    const int kr = (lane >> 4) * 8 + (lane & 7);
    const int kc = ((lane >> 3) & 1) * 8;

    // ---- QK^T: 7 n-tiles x 2 k-steps per warp ----
    float acc[7][4] = {};
    #pragma unroll
    for (int ks = 0; ks < 2; ks++) {
        const int kb16 = ks * 16;
        uint32_t aq[4];
        LDSM_X4(aq, sQ + (uint32_t)((w * 16 + xr) * 40 + kb16 + xc) * 2);
        uint32_t bk[4][4];
        #pragma unroll
        for (int pr = 0; pr < 4; pr++)
            LDSM_X4(bk[pr], sK + (uint32_t)((pr * 16 + kr) * 40 + kb16 + kc) * 2);
        #pragma unroll
        for (int nt = 0; nt < 7; nt++)
            mma16816(acc[nt], aq, &bk[nt >> 1][(nt & 1) * 2]);
    }

    // ---- bias+mask add; mask cols >= 49 (assignment kills garbage/NaN) ----
    const int r0 = w * 16 + (lane >> 2);      // rows r0, r0+8
    const int c0 = (lane & 3) * 2;
    #pragma unroll
    for (int nt = 0; nt < 7; nt++) {
        const int col = nt * 8 + c0;
        #pragma unroll
        for (int e = 0; e < 4; e++) {
            const int rr = r0 + (e >> 1) * 8;
            const int cc = col + (e & 1);
            if (cc < N_) {
                if (rr < N_) acc[nt][e] += __ldg(&bm[rr * N_ + cc]);
            } else {
                acc[nt][e] = -1e30f;
            }
        }
    }

    // ---- softmax in registers (rows r0, r0+8; quad shuffles) ----
    float mx0 = -1e30f, mx1 = -1e30f;
    #pragma unroll
    for (int nt = 0; nt < 7; nt++) {
        mx0 = fmaxf(mx0, fmaxf(acc[nt][0], acc[nt][1]));
        mx1 = fmaxf(mx1, fmaxf(acc[nt][2], acc[nt][3]));
    }
    mx0 = fmaxf(mx0, __shfl_xor_sync(~0u, mx0, 1));
    mx0 = fmaxf(mx0, __shfl_xor_sync(~0u, mx0, 2));
    mx1 = fmaxf(mx1, __shfl_xor_sync(~0u, mx1, 1));
    mx1 = fmaxf(mx1, __shfl_xor_sync(~0u, mx1, 2));

    float s0 = 0.f, s1 = 0.f;
    #pragma unroll
    for (int nt = 0; nt < 7; nt++) {
        acc[nt][0] = __expf(acc[nt][0] - mx0);
        acc[nt][1] = __expf(acc[nt][1] - mx0);
        acc[nt][2] = __expf(acc[nt][2] - mx1);
        acc[nt][3] = __expf(acc[nt][3] - mx1);
        s0 += acc[nt][0] + acc[nt][1];
        s1 += acc[nt][2] + acc[nt][3];
    }
    s0 += __shfl_xor_sync(~0u, s0, 1);
    s0 += __shfl_xor_sync(~0u, s0, 2);
    s1 += __shfl_xor_sync(~0u, s1, 1);
    s1 += __shfl_xor_sync(~0u, s1, 2);
    const float inv0 = 1.f / s0, inv1 = 1.f / s1;

    // ---- write P (fp16) ----
    #pragma unroll
    for (int nt = 0; nt < 7; nt++) {
        const int col = nt * 8 + c0;
        *(__half2*)&P[r0 * 72 + col] =
            __halves2half2(__float2half_rn(acc[nt][0] * inv0),
                           __float2half_rn(acc[nt][1] * inv0));
        *(__half2*)&P[(r0 + 8) * 72 + col] =
            __halves2half2(__float2half_rn(acc[nt][2] * inv1),
                           __float2half_rn(acc[nt][3] * inv1));
    }
    __syncwarp();   // PV reads only this warp's P rows

    // ---- PV: K=64 (4 k-steps), 4 d-tiles; trans-ldmatrix on V = B-operand ----
    float o[4][4] = {};
    #pragma unroll
    for (int ks = 0; ks < 4; ks++) {
        uint32_t ap[4];
        LDSM_X4(ap, sP + (uint32_t)((w * 16 + xr) * 72 + ks * 16 + xc) * 2);
        uint32_t bv[2][4];
        #pragma unroll
        for (int pr = 0; pr < 2; pr++)
            LDSM_X4_T(bv[pr], sV + (uint32_t)((ks * 16 + xr) * 40 + pr * 16 + xc) * 2);
        #pragma unroll
        for (int nt = 0; nt < 4; nt++)
            mma16816(o[nt], ap, &bv[nt >> 1][(nt & 1) * 2]);
    }

    // ---- store output (fp16, guarded) ----
    __half* __restrict__ dstBase = &g_aob[p][((size_t)b * N_) * 256 + h * 32];
    #pragma unroll
    for (int nt = 0; nt < 4; nt++) {
        const int d = nt * 8 + c0;
        if (r0 < N_)
            *(__half2*)&dstBase[(size_t)r0 * 256 + d] =
                __halves2half2(__float2half_rn(o[nt][0]), __float2half_rn(o[nt][1]));
        if (r0 + 8 < N_)
            *(__half2*)&dstBase[(size_t)(r0 + 8) * 256 + d] =
                __halves2half2(__float2half_rn(o[nt][2]), __float2half_rn(o[nt][3]));
    }
}

// ---------------- host launcher ----------------
extern "C" void kernel_launch(void* const* d_in, const int* in_sizes, int n_in,
                              void* d_out, int out_size)
{
    const float* x          = (const float*)d_in[0];
    const float* rgb        = (const float*)d_in[1];
    const float* mask       = (const float*)d_in[2];
    const float* w_qkv      = (const float*)d_in[3];
    const float* b_qkv      = (const float*)d_in[4];
    const float* w_qkv_rgb  = (const float*)d_in[5];
    const float* b_qkv_rgb  = (const float*)d_in[6];
    const float* bias_table = (const float*)d_in[7];
    const float* w_proj     = (const float*)d_in[8];
    const float* b_proj     = (const float*)d_in[9];
    const float* w_proj_rgb = (const float*)d_in[10];
    const float* b_proj_rgb = (const float*)d_in[11];
    const int*   rel_idx    = (const int*)d_in[12];
    float* out = (float*)d_out;

    cudaFuncSetAttribute(qkv_hmma,  cudaFuncAttributeMaxDynamicSharedMemorySize, SMEM_SZ);
    cudaFuncSetAttribute(proj_hmma, cudaFuncAttributeMaxDynamicSharedMemorySize, SMEM_SZ);

    conv_w<<<dim3(768, 4), 256>>>(w_qkv, w_qkv_rgb, w_proj, w_proj_rgb);
    prep_bm<<<dim3(NW_, H_), 256>>>(mask, bias_table, rel_idx);
    conv_in<<<dim3(MT, 2), 256>>>(x, rgb);

    qkv_hmma<<<dim3(768 / BN, MT / BM, 2), 256, SMEM_SZ>>>(b_qkv, b_qkv_rgb);

    attn_kernel<<<dim3(B_, H_, 2), 128>>>();

    proj_hmma<<<dim3(256 / BN, MT / BM, 2), 256, SMEM_SZ>>>(b_proj, b_proj_rgb, out);
}

// round 15
// speedup vs baseline: 2.3766x; 1.1385x over previous
#include <cuda_runtime.h>
#include <cuda_fp16.h>
#include <cstdint>

#define B_  4096
#define N_  49
#define H_  8
#define NW_ 64
#define MT  (B_ * N_)              // 200704 rows
#define SZ_AO ((size_t)MT * 256)
#define NN2 (N_ * N_)              // 2401

#define SCALE_F 0.17677669529663687f

// ---------------- scratch (device globals; no runtime alloc) ----------------
__device__ __half g_A[2][(size_t)MT * 256];     // input fp16
__device__ __half g_Wqkv[2][768 * 256];         // Wt[n][k] fp16
__device__ __half g_Wproj[2][256 * 256];
__device__ __half g_lin[2][(size_t)MT * 768];   // qkv linear out fp16 (q|k|v)
__device__ __half g_aob[2][(size_t)MT * 256];   // attn out fp16
__device__ float  g_bm[NW_ * H_ * NN2];         // combined bias+mask

// ---------------- GEMM config (proven) ----------------
#define BM 128
#define BN 128
#define SA_STR 40
#define SB_STR 264

struct GSmem {
    __align__(16) __half B[BN * SB_STR];
    __align__(16) __half A[4][BM * SA_STR];
};
#define SMEM_SZ ((int)sizeof(GSmem))

__device__ __forceinline__ void cp16(uint32_t dst, const void* src) {
    asm volatile("cp.async.cg.shared.global [%0], [%1], 16;" :: "r"(dst), "l"(src));
}
__device__ __forceinline__ void cp_commit() {
    asm volatile("cp.async.commit_group;" ::: "memory");
}
template<int NN> __device__ __forceinline__ void cp_wait() {
    asm volatile("cp.async.wait_group %0;" :: "n"(NN) : "memory");
}

__device__ __forceinline__ void mma16816(float* d, const uint32_t* a, const uint32_t* b) {
    asm volatile(
        "mma.sync.aligned.m16n8k16.row.col.f32.f16.f16.f32 "
        "{%0,%1,%2,%3}, {%4,%5,%6,%7}, {%8,%9}, {%0,%1,%2,%3};"
        : "+f"(d[0]), "+f"(d[1]), "+f"(d[2]), "+f"(d[3])
        : "r"(a[0]), "r"(a[1]), "r"(a[2]), "r"(a[3]), "r"(b[0]), "r"(b[1]));
}

#define LDSM_X4(r, addr)                                                     \
    asm volatile("ldmatrix.sync.aligned.m8n8.x4.shared.b16 {%0,%1,%2,%3}, [%4];" \
        : "=r"((r)[0]), "=r"((r)[1]), "=r"((r)[2]), "=r"((r)[3]) : "r"(addr))

#define LDSM_X4_T(r, addr)                                                   \
    asm volatile("ldmatrix.sync.aligned.m8n8.x4.trans.shared.b16 {%0,%1,%2,%3}, [%4];" \
        : "=r"((r)[0]), "=r"((r)[1]), "=r"((r)[2]), "=r"((r)[3]) : "r"(addr))

// GEMM mainloop, templated on the A K-dimension (chunks of 32).
template<int KD>
__device__ __forceinline__ void gemm_main(
    GSmem& sm, const __half* __restrict__ A, const __half* __restrict__ W,
    int bm, int bn, float acc[4][4][4])
{
    constexpr int NCH = KD / 32;
    const int tid = threadIdx.x;
    const uint32_t sB = (uint32_t)__cvta_generic_to_shared(sm.B);
    const uint32_t sA = (uint32_t)__cvta_generic_to_shared(sm.A);

    #pragma unroll
    for (int i = 0; i < 16; i++) {
        int idx = tid + i * 256;
        int r = idx >> 5, g = idx & 31;
        cp16(sB + (uint32_t)(r * SB_STR + g * 8) * 2,
             W + (size_t)(bn + r) * 256 + g * 8);
    }
    cp_commit();

    auto issueA = [&](int c) {
        uint32_t dst = sA + (uint32_t)((c & 3) * BM * SA_STR) * 2;
        #pragma unroll
        for (int i = 0; i < 2; i++) {
            int idx = tid + i * 256;
            int r = idx >> 2, g = idx & 3;
            cp16(dst + (uint32_t)(r * SA_STR + g * 8) * 2,
                 A + (size_t)(bm + r) * KD + c * 32 + g * 8);
        }
        cp_commit();
    };
    issueA(0); issueA(1); issueA(2);

    const int lane = tid & 31;
    const int wm = (tid >> 5) & 1, wn = tid >> 6;

    const int a_row = wm * 64 + (lane & 7) + ((lane >> 3) & 1) * 8;
    const int a_col = (lane >> 4) * 8;
    const int b_row = wn * 32 + (lane >> 4) * 8 + (lane & 7);
    const int b_col = ((lane >> 3) & 1) * 8;

    auto compute = [&](int c) {
        const uint32_t aBase = sA + (uint32_t)((c & 3) * BM * SA_STR) * 2;
        const uint32_t bBase = sB + (uint32_t)((c & 7) * 32) * 2;
        #pragma unroll
        for (int ks = 0; ks < 2; ks++) {
            const int kb = ks * 16;
            uint32_t af[4][4], bf[2][4];
            #pragma unroll
            for (int mt = 0; mt < 4; mt++)
                LDSM_X4(af[mt],
                        aBase + (uint32_t)((a_row + mt * 16) * SA_STR + kb + a_col) * 2);
            #pragma unroll
            for (int pr = 0; pr < 2; pr++)
                LDSM_X4(bf[pr],
                        bBase + (uint32_t)((b_row + pr * 16) * SB_STR + kb + b_col) * 2);
            #pragma unroll
            for (int mt = 0; mt < 4; mt++)
                #pragma unroll
                for (int nt = 0; nt < 4; nt++)
                    mma16816(acc[mt][nt], af[mt], &bf[nt >> 1][(nt & 1) * 2]);
        }
    };

    for (int c = 0; c < NCH - 3; c++) {
        cp_wait<2>();
        __syncthreads();
        issueA(c + 3);
        compute(c);
    }
    cp_wait<2>(); __syncthreads(); compute(NCH - 3);
    cp_wait<1>(); __syncthreads(); compute(NCH - 2);
    cp_wait<0>(); __syncthreads(); compute(NCH - 1);
}

// ---------------- GEMM kernels ----------------
__global__ __launch_bounds__(256, 2) void qkv_hmma(
    const float* __restrict__ b0, const float* __restrict__ b1)
{
    extern __shared__ char smem_raw[];
    GSmem& sm = *(GSmem*)smem_raw;
    const int stream = blockIdx.z;
    const int bn = blockIdx.x * BN;
    const int bm = blockIdx.y * BM;

    float acc[4][4][4] = {};
    gemm_main<256>(sm, g_A[stream], g_Wqkv[stream], bm, bn, acc);

    const float* __restrict__ bias = stream ? b1 : b0;
    __half* __restrict__ O = g_lin[stream];
    const int lane = threadIdx.x & 31;
    const int wm = (threadIdx.x >> 5) & 1, wn = threadIdx.x >> 6;
    const float sc = (bn < 256) ? SCALE_F : 1.0f;

    #pragma unroll
    for (int mt = 0; mt < 4; mt++) {
        const int r = bm + wm * 64 + mt * 16 + (lane >> 2);
        #pragma unroll
        for (int nt = 0; nt < 4; nt++) {
            const int col = bn + wn * 32 + nt * 8 + (lane & 3) * 2;
            const float bx = bias[col], by = bias[col + 1];
            *(__half2*)&O[(size_t)r * 768 + col] =
                __halves2half2(__float2half_rn((acc[mt][nt][0] + bx) * sc),
                               __float2half_rn((acc[mt][nt][1] + by) * sc));
            *(__half2*)&O[(size_t)(r + 8) * 768 + col] =
                __halves2half2(__float2half_rn((acc[mt][nt][2] + bx) * sc),
                               __float2half_rn((acc[mt][nt][3] + by) * sc));
        }
    }
}

__global__ __launch_bounds__(256, 2) void proj_hmma(
    const float* __restrict__ bp0, const float* __restrict__ bp1,
    float* __restrict__ out)
{
    extern __shared__ char smem_raw[];
    GSmem& sm = *(GSmem*)smem_raw;
    const int p = blockIdx.z;
    const int bn = blockIdx.x * BN;
    const int bm = blockIdx.y * BM;

    float acc[4][4][4] = {};
    gemm_main<256>(sm, g_aob[p], g_Wproj[p], bm, bn, acc);

    const float* __restrict__ bias = p ? bp1 : bp0;
    float* __restrict__ O = out + (size_t)p * SZ_AO;
    const int lane = threadIdx.x & 31;
    const int wm = (threadIdx.x >> 5) & 1, wn = threadIdx.x >> 6;

    #pragma unroll
    for (int mt = 0; mt < 4; mt++) {
        const int r = bm + wm * 64 + mt * 16 + (lane >> 2);
        #pragma unroll
        for (int nt = 0; nt < 4; nt++) {
            const int col = bn + wn * 32 + nt * 8 + (lane & 3) * 2;
            const float bx = bias[col], by = bias[col + 1];
            float2 v0 = { acc[mt][nt][0] + bx, acc[mt][nt][1] + by };
            float2 v1 = { acc[mt][nt][2] + bx, acc[mt][nt][3] + by };
            *(float2*)&O[(size_t)r * 256 + col]       = v0;
            *(float2*)&O[(size_t)(r + 8) * 256 + col] = v1;
        }
    }
}

// ---------------- conversion / precompute kernels ----------------
__global__ __launch_bounds__(256) void conv_in(
    const float* __restrict__ x, const float* __restrict__ rgb)
{
    const int s = blockIdx.y;
    const float* __restrict__ src = s ? rgb : x;
    size_t idx = ((size_t)blockIdx.x * 256 + threadIdx.x) * 4;
    float4 v = *(const float4*)(src + idx);
    __half2 h0 = __halves2half2(__float2half_rn(v.x), __float2half_rn(v.y));
    __half2 h1 = __halves2half2(__float2half_rn(v.z), __float2half_rn(v.w));
    *(__half2*)&g_A[s][idx]     = h0;
    *(__half2*)&g_A[s][idx + 2] = h1;
}

__global__ __launch_bounds__(256) void conv_w(
    const float* __restrict__ w_qkv, const float* __restrict__ w_qkv_rgb,
    const float* __restrict__ w_proj, const float* __restrict__ w_proj_rgb)
{
    const int which = blockIdx.y;
    const float* src; __half* dst; int NC;
    switch (which) {
        case 0: src = w_qkv;       dst = g_Wqkv[0];  NC = 768; break;
        case 1: src = w_qkv_rgb;   dst = g_Wqkv[1];  NC = 768; break;
        case 2: src = w_proj;      dst = g_Wproj[0]; NC = 256; break;
        default: src = w_proj_rgb; dst = g_Wproj[1]; NC = 256; break;
    }
    int idx = blockIdx.x * 256 + threadIdx.x;
    if (idx >= 256 * NC) return;
    int k = idx / NC, n = idx % NC;
    dst[(size_t)n * 256 + k] = __float2half_rn(src[idx]);
}

__global__ __launch_bounds__(256) void prep_bm(
    const float* __restrict__ mask, const float* __restrict__ bias_table,
    const int* __restrict__ rel_idx)
{
    const int w = blockIdx.x, h = blockIdx.y;
    float* __restrict__ dst = g_bm + (size_t)(w * H_ + h) * NN2;
    const float* __restrict__ msk = mask + (size_t)w * NN2;
    for (int idx = threadIdx.x; idx < NN2; idx += 256)
        dst[idx] = bias_table[rel_idx[idx] * H_ + h] + msk[idx];
}

// ---------------- fused attention (HMMA, both paths per block) --------------
// One block per (b, h): 256 threads = 8 warps. Warps 0-3 -> p=0, warps 4-7 ->
// p=1; each 4-warp group runs the proven R13/R14 attention on its own smem half.
__global__ __launch_bounds__(256) void attn_kernel()
{
    const int b = blockIdx.x, h = blockIdx.y;
    const int tid = threadIdx.x;
    const int grp = tid >> 7;            // 0 or 1 = path p
    const int gt  = tid & 127;           // thread within group

    const int p = grp;
    const int qs = p ^ 1, kv = p;
    const __half* __restrict__ qb = g_lin[qs] + (size_t)b * N_ * 768 + h * 32;
    const __half* __restrict__ kb = g_lin[kv] + (size_t)b * N_ * 768 + 256 + h * 32;
    const __half* __restrict__ vb = g_lin[kv] + (size_t)b * N_ * 768 + 512 + h * 32;
    const float* __restrict__ bm = g_bm + (size_t)((b & (NW_ - 1)) * H_ + h) * NN2;

    __shared__ __align__(16) __half Qs[2][64 * 40];
    __shared__ __align__(16) __half Ks[2][64 * 40];
    __shared__ __align__(16) __half Vs[2][64 * 40];
    __shared__ __align__(16) __half P [2][64 * 72];

    // Load Q,K,V fp16 (49 rows x 32 d) for this group's path
    for (int i = gt; i < N_ * 8; i += 128) {
        int n = i >> 3, dp = (i & 7) * 4;
        *(uint2*)&Qs[grp][n * 40 + dp] = *(const uint2*)(qb + n * 768 + dp);
        *(uint2*)&Ks[grp][n * 40 + dp] = *(const uint2*)(kb + n * 768 + dp);
        *(uint2*)&Vs[grp][n * 40 + dp] = *(const uint2*)(vb + n * 768 + dp);
    }
    // Zero V pad rows 49..63 (NaN-proof)
    for (int i = gt; i < 15 * 40; i += 128)
        Vs[grp][49 * 40 + i] = __ushort_as_half(0);
    // Zero P cols 56..63 for all 64 rows
    {
        int r = gt >> 1, c = (gt & 1) * 4;
        *(uint2*)&P[grp][r * 72 + 56 + c] = make_uint2(0u, 0u);
    }
    __syncthreads();

    const int lane = tid & 31, w = (tid >> 5) & 3;   // warp within group
    const uint32_t sQ = (uint32_t)__cvta_generic_to_shared(Qs[grp]);
    const uint32_t sK = (uint32_t)__cvta_generic_to_shared(Ks[grp]);
    const uint32_t sV = (uint32_t)__cvta_generic_to_shared(Vs[grp]);
    const uint32_t sP = (uint32_t)__cvta_generic_to_shared(P[grp]);

    const int xr = (lane & 7) + ((lane >> 3) & 1) * 8;   // A-operand mapping
    const int xc = (lane >> 4) * 8;
    const int kr = (lane >> 4) * 8 + (lane & 7);          // B-operand mapping
    const int kc = ((lane >> 3) & 1) * 8;

    // ---- QK^T: 7 n-tiles x 2 k-steps per warp ----
    float acc[7][4] = {};
    #pragma unroll
    for (int ks = 0; ks < 2; ks++) {
        const int kb16 = ks * 16;
        uint32_t aq[4];
        LDSM_X4(aq, sQ + (uint32_t)((w * 16 + xr) * 40 + kb16 + xc) * 2);
        uint32_t bk[4][4];
        #pragma unroll
        for (int pr = 0; pr < 4; pr++)
            LDSM_X4(bk[pr], sK + (uint32_t)((pr * 16 + kr) * 40 + kb16 + kc) * 2);
        #pragma unroll
        for (int nt = 0; nt < 7; nt++)
            mma16816(acc[nt], aq, &bk[nt >> 1][(nt & 1) * 2]);
    }

    // ---- bias+mask add; mask cols >= 49 ----
    const int r0 = w * 16 + (lane >> 2);
    const int c0 = (lane & 3) * 2;
    #pragma unroll
    for (int nt = 0; nt < 7; nt++) {
        const int col = nt * 8 + c0;
        #pragma unroll
        for (int e = 0; e < 4; e++) {
            const int rr = r0 + (e >> 1) * 8;
            const int cc = col + (e & 1);
            if (cc < N_) {
                if (rr < N_) acc[nt][e] += __ldg(&bm[rr * N_ + cc]);
            } else {
                acc[nt][e] = -1e30f;
            }
        }
    }

    // ---- softmax in registers ----
    float mx0 = -1e30f, mx1 = -1e30f;
    #pragma unroll
    for (int nt = 0; nt < 7; nt++) {
        mx0 = fmaxf(mx0, fmaxf(acc[nt][0], acc[nt][1]));
        mx1 = fmaxf(mx1, fmaxf(acc[nt][2], acc[nt][3]));
    }
    mx0 = fmaxf(mx0, __shfl_xor_sync(~0u, mx0, 1));
    mx0 = fmaxf(mx0, __shfl_xor_sync(~0u, mx0, 2));
    mx1 = fmaxf(mx1, __shfl_xor_sync(~0u, mx1, 1));
    mx1 = fmaxf(mx1, __shfl_xor_sync(~0u, mx1, 2));

    float s0 = 0.f, s1 = 0.f;
    #pragma unroll
    for (int nt = 0; nt < 7; nt++) {
        acc[nt][0] = __expf(acc[nt][0] - mx0);
        acc[nt][1] = __expf(acc[nt][1] - mx0);
        acc[nt][2] = __expf(acc[nt][2] - mx1);
        acc[nt][3] = __expf(acc[nt][3] - mx1);
        s0 += acc[nt][0] + acc[nt][1];
        s1 += acc[nt][2] + acc[nt][3];
    }
    s0 += __shfl_xor_sync(~0u, s0, 1);
    s0 += __shfl_xor_sync(~0u, s0, 2);
    s1 += __shfl_xor_sync(~0u, s1, 1);
    s1 += __shfl_xor_sync(~0u, s1, 2);
    const float inv0 = 1.f / s0, inv1 = 1.f / s1;

    // ---- write P (fp16) ----
    #pragma unroll
    for (int nt = 0; nt < 7; nt++) {
        const int col = nt * 8 + c0;
        *(__half2*)&P[grp][r0 * 72 + col] =
            __halves2half2(__float2half_rn(acc[nt][0] * inv0),
                           __float2half_rn(acc[nt][1] * inv0));
        *(__half2*)&P[grp][(r0 + 8) * 72 + col] =
            __halves2half2(__float2half_rn(acc[nt][2] * inv1),
                           __float2half_rn(acc[nt][3] * inv1));
    }
    __syncwarp();   // PV reads only this warp's P rows

    // ---- PV: K=64 (4 k-steps), 4 d-tiles ----
    float o[4][4] = {};
    #pragma unroll
    for (int ks = 0; ks < 4; ks++) {
        uint32_t ap[4];
        LDSM_X4(ap, sP + (uint32_t)((w * 16 + xr) * 72 + ks * 16 + xc) * 2);
        uint32_t bv[2][4];
        #pragma unroll
        for (int pr = 0; pr < 2; pr++)
            LDSM_X4_T(bv[pr], sV + (uint32_t)((ks * 16 + xr) * 40 + pr * 16 + xc) * 2);
        #pragma unroll
        for (int nt = 0; nt < 4; nt++)
            mma16816(o[nt], ap, &bv[nt >> 1][(nt & 1) * 2]);
    }

    // ---- store output (fp16, guarded) ----
    __half* __restrict__ dstBase = &g_aob[p][((size_t)b * N_) * 256 + h * 32];
    #pragma unroll
    for (int nt = 0; nt < 4; nt++) {
        const int d = nt * 8 + c0;
        if (r0 < N_)
            *(__half2*)&dstBase[(size_t)r0 * 256 + d] =
                __halves2half2(__float2half_rn(o[nt][0]), __float2half_rn(o[nt][1]));
        if (r0 + 8 < N_)
            *(__half2*)&dstBase[(size_t)(r0 + 8) * 256 + d] =
                __halves2half2(__float2half_rn(o[nt][2]), __float2half_rn(o[nt][3]));
    }
}

// ---------------- host launcher ----------------
extern "C" void kernel_launch(void* const* d_in, const int* in_sizes, int n_in,
                              void* d_out, int out_size)
{
    const float* x          = (const float*)d_in[0];
    const float* rgb        = (const float*)d_in[1];
    const float* mask       = (const float*)d_in[2];
    const float* w_qkv      = (const float*)d_in[3];
    const float* b_qkv      = (const float*)d_in[4];
    const float* w_qkv_rgb  = (const float*)d_in[5];
    const float* b_qkv_rgb  = (const float*)d_in[6];
    const float* bias_table = (const float*)d_in[7];
    const float* w_proj     = (const float*)d_in[8];
    const float* b_proj     = (const float*)d_in[9];
    const float* w_proj_rgb = (const float*)d_in[10];
    const float* b_proj_rgb = (const float*)d_in[11];
    const int*   rel_idx    = (const int*)d_in[12];
    float* out = (float*)d_out;

    cudaFuncSetAttribute(qkv_hmma,  cudaFuncAttributeMaxDynamicSharedMemorySize, SMEM_SZ);
    cudaFuncSetAttribute(proj_hmma, cudaFuncAttributeMaxDynamicSharedMemorySize, SMEM_SZ);

    conv_w<<<dim3(768, 4), 256>>>(w_qkv, w_qkv_rgb, w_proj, w_proj_rgb);
    prep_bm<<<dim3(NW_, H_), 256>>>(mask, bias_table, rel_idx);
    conv_in<<<dim3(MT / 4, 2), 256>>>(x, rgb);

    qkv_hmma<<<dim3(768 / BN, MT / BM, 2), 256, SMEM_SZ>>>(b_qkv, b_qkv_rgb);

    attn_kernel<<<dim3(B_, H_), 256>>>();

    proj_hmma<<<dim3(256 / BN, MT / BM, 2), 256, SMEM_SZ>>>(b_proj, b_proj_rgb, out);
}

// round 16
// speedup vs baseline: 2.3838x; 1.0030x over previous
#include <cuda_runtime.h>
#include <cuda_fp16.h>
#include <cstdint>

#define B_  4096
#define N_  49
#define H_  8
#define NW_ 64
#define MT  (B_ * N_)              // 200704 rows
#define SZ_AO ((size_t)MT * 256)
#define NN2 (N_ * N_)              // 2401

#define SCALE_F 0.17677669529663687f
#define MTILES 16                   // M-tiles per persistent GEMM CTA

// ---------------- scratch (device globals; no runtime alloc) ----------------
__device__ __half g_A[2][(size_t)MT * 256];     // input fp16
__device__ __half g_Wqkv[2][768 * 256];         // Wt[n][k] fp16
__device__ __half g_Wproj[2][256 * 256];
__device__ __half g_lin[2][(size_t)MT * 768];   // qkv linear out fp16 (q|k|v)
__device__ __half g_aob[2][(size_t)MT * 256];   // attn out fp16
__device__ float  g_bm[NW_ * H_ * NN2];         // combined bias+mask

// ---------------- GEMM config (proven) ----------------
#define BM 128
#define BN 128
#define SA_STR 40
#define SB_STR 264

struct GSmem {
    __align__(16) __half B[BN * SB_STR];
    __align__(16) __half A[4][BM * SA_STR];
};
#define SMEM_SZ ((int)sizeof(GSmem))

__device__ __forceinline__ void cp16(uint32_t dst, const void* src) {
    asm volatile("cp.async.cg.shared.global [%0], [%1], 16;" :: "r"(dst), "l"(src));
}
__device__ __forceinline__ void cp_commit() {
    asm volatile("cp.async.commit_group;" ::: "memory");
}
template<int NN> __device__ __forceinline__ void cp_wait() {
    asm volatile("cp.async.wait_group %0;" :: "n"(NN) : "memory");
}

__device__ __forceinline__ void mma16816(float* d, const uint32_t* a, const uint32_t* b) {
    asm volatile(
        "mma.sync.aligned.m16n8k16.row.col.f32.f16.f16.f32 "
        "{%0,%1,%2,%3}, {%4,%5,%6,%7}, {%8,%9}, {%0,%1,%2,%3};"
        : "+f"(d[0]), "+f"(d[1]), "+f"(d[2]), "+f"(d[3])
        : "r"(a[0]), "r"(a[1]), "r"(a[2]), "r"(a[3]), "r"(b[0]), "r"(b[1]));
}

#define LDSM_X4(r, addr)                                                     \
    asm volatile("ldmatrix.sync.aligned.m8n8.x4.shared.b16 {%0,%1,%2,%3}, [%4];" \
        : "=r"((r)[0]), "=r"((r)[1]), "=r"((r)[2]), "=r"((r)[3]) : "r"(addr))

#define LDSM_X4_T(r, addr)                                                   \
    asm volatile("ldmatrix.sync.aligned.m8n8.x4.trans.shared.b16 {%0,%1,%2,%3}, [%4];" \
        : "=r"((r)[0]), "=r"((r)[1]), "=r"((r)[2]), "=r"((r)[3]) : "r"(addr))

// Persistent multi-tile GEMM: B panel loaded once; A pipeline runs continuously
// across MTILES M-tiles (global chunk g; stage g&3, B col (g&7)*32, K=256).
// Per-tile inner math identical to the proven single-tile version.
template<class Epi>
__device__ __forceinline__ void gemm_multi(
    GSmem& sm, const __half* __restrict__ A, const __half* __restrict__ W,
    int bn, int m0, Epi epi)
{
    const int tid = threadIdx.x;
    const uint32_t sB = (uint32_t)__cvta_generic_to_shared(sm.B);
    const uint32_t sA = (uint32_t)__cvta_generic_to_shared(sm.A);

    #pragma unroll
    for (int i = 0; i < 16; i++) {
        int idx = tid + i * 256;
        int r = idx >> 5, g = idx & 31;
        cp16(sB + (uint32_t)(r * SB_STR + g * 8) * 2,
             W + (size_t)(bn + r) * 256 + g * 8);
    }
    cp_commit();

    auto issueA = [&](int g) {
        uint32_t dst = sA + (uint32_t)((g & 3) * BM * SA_STR) * 2;
        const int bm = (m0 + (g >> 3)) * BM;
        const int k0 = (g & 7) * 32;
        #pragma unroll
        for (int i = 0; i < 2; i++) {
            int idx = tid + i * 256;
            int r = idx >> 2, gg = idx & 3;
            cp16(dst + (uint32_t)(r * SA_STR + gg * 8) * 2,
                 A + (size_t)(bm + r) * 256 + k0 + gg * 8);
        }
        cp_commit();
    };
    issueA(0); issueA(1); issueA(2);

    const int lane = tid & 31;
    const int wm = (tid >> 5) & 1, wn = tid >> 6;

    const int a_row = wm * 64 + (lane & 7) + ((lane >> 3) & 1) * 8;
    const int a_col = (lane >> 4) * 8;
    const int b_row = wn * 32 + (lane >> 4) * 8 + (lane & 7);
    const int b_col = ((lane >> 3) & 1) * 8;

    float acc[4][4][4] = {};

    auto compute = [&](int g) {
        const uint32_t aBase = sA + (uint32_t)((g & 3) * BM * SA_STR) * 2;
        const uint32_t bBase = sB + (uint32_t)((g & 7) * 32) * 2;
        #pragma unroll
        for (int ks = 0; ks < 2; ks++) {
            const int kb = ks * 16;
            uint32_t af[4][4], bf[2][4];
            #pragma unroll
            for (int mt = 0; mt < 4; mt++)
                LDSM_X4(af[mt],
                        aBase + (uint32_t)((a_row + mt * 16) * SA_STR + kb + a_col) * 2);
            #pragma unroll
            for (int pr = 0; pr < 2; pr++)
                LDSM_X4(bf[pr],
                        bBase + (uint32_t)((b_row + pr * 16) * SB_STR + kb + b_col) * 2);
            #pragma unroll
            for (int mt = 0; mt < 4; mt++)
                #pragma unroll
                for (int nt = 0; nt < 4; nt++)
                    mma16816(acc[mt][nt], af[mt], &bf[nt >> 1][(nt & 1) * 2]);
        }
    };

    const int T = MTILES * 8;
    for (int g = 0; g < T; g++) {
        if (g < T - 3)       { cp_wait<2>(); __syncthreads(); issueA(g + 3); }
        else if (g == T - 3) { cp_wait<2>(); __syncthreads(); }
        else if (g == T - 2) { cp_wait<1>(); __syncthreads(); }
        else                 { cp_wait<0>(); __syncthreads(); }
        compute(g);
        if ((g & 7) == 7) {
            epi((m0 + (g >> 3)) * BM, acc);
            #pragma unroll
            for (int i = 0; i < 4; i++)
                #pragma unroll
                for (int j = 0; j < 4; j++)
                    #pragma unroll
                    for (int e = 0; e < 4; e++) acc[i][j][e] = 0.f;
        }
    }
}

// ---------------- GEMM kernels ----------------
__global__ __launch_bounds__(256, 2) void qkv_hmma(
    const float* __restrict__ b0, const float* __restrict__ b1)
{
    extern __shared__ char smem_raw[];
    GSmem& sm = *(GSmem*)smem_raw;
    const int stream = blockIdx.z;
    const int bn = blockIdx.x * BN;
    const int m0 = blockIdx.y * MTILES;

    const float* __restrict__ bias = stream ? b1 : b0;
    __half* __restrict__ O = g_lin[stream];
    const int lane = threadIdx.x & 31;
    const int wm = (threadIdx.x >> 5) & 1, wn = threadIdx.x >> 6;
    const float sc = (bn < 256) ? SCALE_F : 1.0f;

    gemm_multi(sm, g_A[stream], g_Wqkv[stream], bn, m0,
        [&](int bm, float acc[4][4][4]) {
            #pragma unroll
            for (int mt = 0; mt < 4; mt++) {
                const int r = bm + wm * 64 + mt * 16 + (lane >> 2);
                #pragma unroll
                for (int nt = 0; nt < 4; nt++) {
                    const int col = bn + wn * 32 + nt * 8 + (lane & 3) * 2;
                    const float bx = bias[col], by = bias[col + 1];
                    *(__half2*)&O[(size_t)r * 768 + col] =
                        __halves2half2(__float2half_rn((acc[mt][nt][0] + bx) * sc),
                                       __float2half_rn((acc[mt][nt][1] + by) * sc));
                    *(__half2*)&O[(size_t)(r + 8) * 768 + col] =
                        __halves2half2(__float2half_rn((acc[mt][nt][2] + bx) * sc),
                                       __float2half_rn((acc[mt][nt][3] + by) * sc));
                }
            }
        });
}

__global__ __launch_bounds__(256, 2) void proj_hmma(
    const float* __restrict__ bp0, const float* __restrict__ bp1,
    float* __restrict__ out)
{
    extern __shared__ char smem_raw[];
    GSmem& sm = *(GSmem*)smem_raw;
    const int p = blockIdx.z;
    const int bn = blockIdx.x * BN;
    const int m0 = blockIdx.y * MTILES;

    const float* __restrict__ bias = p ? bp1 : bp0;
    float* __restrict__ O = out + (size_t)p * SZ_AO;
    const int lane = threadIdx.x & 31;
    const int wm = (threadIdx.x >> 5) & 1, wn = threadIdx.x >> 6;

    gemm_multi(sm, g_aob[p], g_Wproj[p], bn, m0,
        [&](int bm, float acc[4][4][4]) {
            #pragma unroll
            for (int mt = 0; mt < 4; mt++) {
                const int r = bm + wm * 64 + mt * 16 + (lane >> 2);
                #pragma unroll
                for (int nt = 0; nt < 4; nt++) {
                    const int col = bn + wn * 32 + nt * 8 + (lane & 3) * 2;
                    const float bx = bias[col], by = bias[col + 1];
                    float2 v0 = { acc[mt][nt][0] + bx, acc[mt][nt][1] + by };
                    float2 v1 = { acc[mt][nt][2] + bx, acc[mt][nt][3] + by };
                    *(float2*)&O[(size_t)r * 256 + col]       = v0;
                    *(float2*)&O[(size_t)(r + 8) * 256 + col] = v1;
                }
            }
        });
}

// ---------------- conversion / precompute kernels ----------------
__global__ __launch_bounds__(256) void conv_in(
    const float* __restrict__ x, const float* __restrict__ rgb)
{
    const int s = blockIdx.y;
    const float* __restrict__ src = s ? rgb : x;
    size_t idx = ((size_t)blockIdx.x * 256 + threadIdx.x) * 4;
    float4 v = *(const float4*)(src + idx);
    __half2 h0 = __halves2half2(__float2half_rn(v.x), __float2half_rn(v.y));
    __half2 h1 = __halves2half2(__float2half_rn(v.z), __float2half_rn(v.w));
    *(__half2*)&g_A[s][idx]     = h0;
    *(__half2*)&g_A[s][idx + 2] = h1;
}

__global__ __launch_bounds__(256) void conv_w(
    const float* __restrict__ w_qkv, const float* __restrict__ w_qkv_rgb,
    const float* __restrict__ w_proj, const float* __restrict__ w_proj_rgb)
{
    const int which = blockIdx.y;
    const float* src; __half* dst; int NC;
    switch (which) {
        case 0: src = w_qkv;       dst = g_Wqkv[0];  NC = 768; break;
        case 1: src = w_qkv_rgb;   dst = g_Wqkv[1];  NC = 768; break;
        case 2: src = w_proj;      dst = g_Wproj[0]; NC = 256; break;
        default: src = w_proj_rgb; dst = g_Wproj[1]; NC = 256; break;
    }
    int idx = blockIdx.x * 256 + threadIdx.x;
    if (idx >= 256 * NC) return;
    int k = idx / NC, n = idx % NC;
    dst[(size_t)n * 256 + k] = __float2half_rn(src[idx]);
}

__global__ __launch_bounds__(256) void prep_bm(
    const float* __restrict__ mask, const float* __restrict__ bias_table,
    const int* __restrict__ rel_idx)
{
    const int w = blockIdx.x, h = blockIdx.y;
    float* __restrict__ dst = g_bm + (size_t)(w * H_ + h) * NN2;
    const float* __restrict__ msk = mask + (size_t)w * NN2;
    for (int idx = threadIdx.x; idx < NN2; idx += 256)
        dst[idx] = bias_table[rel_idx[idx] * H_ + h] + msk[idx];
}

// ---------------- fused attention (HMMA, both paths per block) --------------
__global__ __launch_bounds__(256) void attn_kernel()
{
    const int b = blockIdx.x, h = blockIdx.y;
    const int tid = threadIdx.x;
    const int grp = tid >> 7;            // 0 or 1 = path p
    const int gt  = tid & 127;

    const int p = grp;
    const int qs = p ^ 1, kv = p;
    const __half* __restrict__ qb = g_lin[qs] + (size_t)b * N_ * 768 + h * 32;
    const __half* __restrict__ kb = g_lin[kv] + (size_t)b * N_ * 768 + 256 + h * 32;
    const __half* __restrict__ vb = g_lin[kv] + (size_t)b * N_ * 768 + 512 + h * 32;
    const float* __restrict__ bm = g_bm + (size_t)((b & (NW_ - 1)) * H_ + h) * NN2;

    __shared__ __align__(16) __half Qs[2][64 * 40];
    __shared__ __align__(16) __half Ks[2][64 * 40];
    __shared__ __align__(16) __half Vs[2][64 * 40];
    __shared__ __align__(16) __half P [2][64 * 72];

    for (int i = gt; i < N_ * 8; i += 128) {
        int n = i >> 3, dp = (i & 7) * 4;
        *(uint2*)&Qs[grp][n * 40 + dp] = *(const uint2*)(qb + n * 768 + dp);
        *(uint2*)&Ks[grp][n * 40 + dp] = *(const uint2*)(kb + n * 768 + dp);
        *(uint2*)&Vs[grp][n * 40 + dp] = *(const uint2*)(vb + n * 768 + dp);
    }
    for (int i = gt; i < 15 * 40; i += 128)
        Vs[grp][49 * 40 + i] = __ushort_as_half(0);
    {
        int r = gt >> 1, c = (gt & 1) * 4;
        *(uint2*)&P[grp][r * 72 + 56 + c] = make_uint2(0u, 0u);
    }
    __syncthreads();

    const int lane = tid & 31, w = (tid >> 5) & 3;
    const uint32_t sQ = (uint32_t)__cvta_generic_to_shared(Qs[grp]);
    const uint32_t sK = (uint32_t)__cvta_generic_to_shared(Ks[grp]);
    const uint32_t sV = (uint32_t)__cvta_generic_to_shared(Vs[grp]);
    const uint32_t sP = (uint32_t)__cvta_generic_to_shared(P[grp]);

    const int xr = (lane & 7) + ((lane >> 3) & 1) * 8;
    const int xc = (lane >> 4) * 8;
    const int kr = (lane >> 4) * 8 + (lane & 7);
    const int kc = ((lane >> 3) & 1) * 8;

    float acc[7][4] = {};
    #pragma unroll
    for (int ks = 0; ks < 2; ks++) {
        const int kb16 = ks * 16;
        uint32_t aq[4];
        LDSM_X4(aq, sQ + (uint32_t)((w * 16 + xr) * 40 + kb16 + xc) * 2);
        uint32_t bk[4][4];
        #pragma unroll
        for (int pr = 0; pr < 4; pr++)
            LDSM_X4(bk[pr], sK + (uint32_t)((pr * 16 + kr) * 40 + kb16 + kc) * 2);
        #pragma unroll
        for (int nt = 0; nt < 7; nt++)
            mma16816(acc[nt], aq, &bk[nt >> 1][(nt & 1) * 2]);
    }

    const int r0 = w * 16 + (lane >> 2);
    const int c0 = (lane & 3) * 2;
    #pragma unroll
    for (int nt = 0; nt < 7; nt++) {
        const int col = nt * 8 + c0;
        #pragma unroll
        for (int e = 0; e < 4; e++) {
            const int rr = r0 + (e >> 1) * 8;
            const int cc = col + (e & 1);
            if (cc < N_) {
                if (rr < N_) acc[nt][e] += __ldg(&bm[rr * N_ + cc]);
            } else {
                acc[nt][e] = -1e30f;
            }
        }
    }

    float mx0 = -1e30f, mx1 = -1e30f;
    #pragma unroll
    for (int nt = 0; nt < 7; nt++) {
        mx0 = fmaxf(mx0, fmaxf(acc[nt][0], acc[nt][1]));
        mx1 = fmaxf(mx1, fmaxf(acc[nt][2], acc[nt][3]));
    }
    mx0 = fmaxf(mx0, __shfl_xor_sync(~0u, mx0, 1));
    mx0 = fmaxf(mx0, __shfl_xor_sync(~0u, mx0, 2));
    mx1 = fmaxf(mx1, __shfl_xor_sync(~0u, mx1, 1));
    mx1 = fmaxf(mx1, __shfl_xor_sync(~0u, mx1, 2));

    float s0 = 0.f, s1 = 0.f;
    #pragma unroll
    for (int nt = 0; nt < 7; nt++) {
        acc[nt][0] = __expf(acc[nt][0] - mx0);
        acc[nt][1] = __expf(acc[nt][1] - mx0);
        acc[nt][2] = __expf(acc[nt][2] - mx1);
        acc[nt][3] = __expf(acc[nt][3] - mx1);
        s0 += acc[nt][0] + acc[nt][1];
        s1 += acc[nt][2] + acc[nt][3];
    }
    s0 += __shfl_xor_sync(~0u, s0, 1);
    s0 += __shfl_xor_sync(~0u, s0, 2);
    s1 += __shfl_xor_sync(~0u, s1, 1);
    s1 += __shfl_xor_sync(~0u, s1, 2);
    const float inv0 = 1.f / s0, inv1 = 1.f / s1;

    #pragma unroll
    for (int nt = 0; nt < 7; nt++) {
        const int col = nt * 8 + c0;
        *(__half2*)&P[grp][r0 * 72 + col] =
            __halves2half2(__float2half_rn(acc[nt][0] * inv0),
                           __float2half_rn(acc[nt][1] * inv0));
        *(__half2*)&P[grp][(r0 + 8) * 72 + col] =
            __halves2half2(__float2half_rn(acc[nt][2] * inv1),
                           __float2half_rn(acc[nt][3] * inv1));
    }
    __syncwarp();

    float o[4][4] = {};
    #pragma unroll
    for (int ks = 0; ks < 4; ks++) {
        uint32_t ap[4];
        LDSM_X4(ap, sP + (uint32_t)((w * 16 + xr) * 72 + ks * 16 + xc) * 2);
        uint32_t bv[2][4];
        #pragma unroll
        for (int pr = 0; pr < 2; pr++)
            LDSM_X4_T(bv[pr], sV + (uint32_t)((ks * 16 + xr) * 40 + pr * 16 + xc) * 2);
        #pragma unroll
        for (int nt = 0; nt < 4; nt++)
            mma16816(o[nt], ap, &bv[nt >> 1][(nt & 1) * 2]);
    }

    __half* __restrict__ dstBase = &g_aob[p][((size_t)b * N_) * 256 + h * 32];
    #pragma unroll
    for (int nt = 0; nt < 4; nt++) {
        const int d = nt * 8 + c0;
        if (r0 < N_)
            *(__half2*)&dstBase[(size_t)r0 * 256 + d] =
                __halves2half2(__float2half_rn(o[nt][0]), __float2half_rn(o[nt][1]));
        if (r0 + 8 < N_)
            *(__half2*)&dstBase[(size_t)(r0 + 8) * 256 + d] =
                __halves2half2(__float2half_rn(o[nt][2]), __float2half_rn(o[nt][3]));
    }
}

// ---------------- host launcher ----------------
extern "C" void kernel_launch(void* const* d_in, const int* in_sizes, int n_in,
                              void* d_out, int out_size)
{
    const float* x          = (const float*)d_in[0];
    const float* rgb        = (const float*)d_in[1];
    const float* mask       = (const float*)d_in[2];
    const float* w_qkv      = (const float*)d_in[3];
    const float* b_qkv      = (const float*)d_in[4];
    const float* w_qkv_rgb  = (const float*)d_in[5];
    const float* b_qkv_rgb  = (const float*)d_in[6];
    const float* bias_table = (const float*)d_in[7];
    const float* w_proj     = (const float*)d_in[8];
    const float* b_proj     = (const float*)d_in[9];
    const float* w_proj_rgb = (const float*)d_in[10];
    const float* b_proj_rgb = (const float*)d_in[11];
    const int*   rel_idx    = (const int*)d_in[12];
    float* out = (float*)d_out;

    cudaFuncSetAttribute(qkv_hmma,  cudaFuncAttributeMaxDynamicSharedMemorySize, SMEM_SZ);
    cudaFuncSetAttribute(proj_hmma, cudaFuncAttributeMaxDynamicSharedMemorySize, SMEM_SZ);

    conv_w<<<dim3(768, 4), 256>>>(w_qkv, w_qkv_rgb, w_proj, w_proj_rgb);
    prep_bm<<<dim3(NW_, H_), 256>>>(mask, bias_table, rel_idx);
    conv_in<<<dim3(MT / 4, 2), 256>>>(x, rgb);

    // MT/BM = 1568 M-tiles; 1568/MTILES = 98 persistent CTAs per (bn, stream)
    qkv_hmma<<<dim3(768 / BN, 1568 / MTILES, 2), 256, SMEM_SZ>>>(b_qkv, b_qkv_rgb);

    attn_kernel<<<dim3(B_, H_), 256>>>();

    proj_hmma<<<dim3(256 / BN, 1568 / MTILES, 2), 256, SMEM_SZ>>>(b_proj, b_proj_rgb, out);
}

// round 17
// speedup vs baseline: 2.4395x; 1.0234x over previous
#include <cuda_runtime.h>
#include <cuda_fp16.h>
#include <cstdint>

#define B_  4096
#define N_  49
#define H_  8
#define NW_ 64
#define MT  (B_ * N_)              // 200704 rows
#define SZ_AO ((size_t)MT * 256)
#define NN2 (N_ * N_)              // 2401
#define BM_STRIDE 56               // padded bm row stride (halves)

#define SCALE_F 0.17677669529663687f
#define MTILES 16                   // M-tiles per persistent GEMM CTA

// ---------------- scratch (device globals; no runtime alloc) ----------------
__device__ __half g_A[2][(size_t)MT * 256];     // input fp16
__device__ __half g_Wqkv[2][768 * 256];         // Wt[n][k] fp16
__device__ __half g_Wproj[2][256 * 256];
__device__ __half g_lin[2][(size_t)MT * 768];   // qkv linear out fp16 (q|k|v)
__device__ __half g_aob[2][(size_t)MT * 256];   // attn out fp16
__device__ __half g_bmh[NW_ * H_ * N_ * BM_STRIDE];  // bias+mask fp16, padded

// ---------------- GEMM config (proven) ----------------
#define BM 128
#define BN 128
#define SA_STR 40
#define SB_STR 264

struct GSmem {
    __align__(16) __half B[BN * SB_STR];
    __align__(16) __half A[4][BM * SA_STR];
};
#define SMEM_SZ ((int)sizeof(GSmem))

__device__ __forceinline__ void cp16(uint32_t dst, const void* src) {
    asm volatile("cp.async.cg.shared.global [%0], [%1], 16;" :: "r"(dst), "l"(src));
}
__device__ __forceinline__ void cp_commit() {
    asm volatile("cp.async.commit_group;" ::: "memory");
}
template<int NN> __device__ __forceinline__ void cp_wait() {
    asm volatile("cp.async.wait_group %0;" :: "n"(NN) : "memory");
}

__device__ __forceinline__ void mma16816(float* d, const uint32_t* a, const uint32_t* b) {
    asm volatile(
        "mma.sync.aligned.m16n8k16.row.col.f32.f16.f16.f32 "
        "{%0,%1,%2,%3}, {%4,%5,%6,%7}, {%8,%9}, {%0,%1,%2,%3};"
        : "+f"(d[0]), "+f"(d[1]), "+f"(d[2]), "+f"(d[3])
        : "r"(a[0]), "r"(a[1]), "r"(a[2]), "r"(a[3]), "r"(b[0]), "r"(b[1]));
}

#define LDSM_X4(r, addr)                                                     \
    asm volatile("ldmatrix.sync.aligned.m8n8.x4.shared.b16 {%0,%1,%2,%3}, [%4];" \
        : "=r"((r)[0]), "=r"((r)[1]), "=r"((r)[2]), "=r"((r)[3]) : "r"(addr))

#define LDSM_X4_T(r, addr)                                                   \
    asm volatile("ldmatrix.sync.aligned.m8n8.x4.trans.shared.b16 {%0,%1,%2,%3}, [%4];" \
        : "=r"((r)[0]), "=r"((r)[1]), "=r"((r)[2]), "=r"((r)[3]) : "r"(addr))

// Persistent multi-tile GEMM. Tile order rotated by `phase` so sibling CTAs on
// the same SM desynchronize their epilogue bursts (tensor pipe fills during
// the other CTA's stores). Per-tile math identical; bit-identical output.
template<class Epi>
__device__ __forceinline__ void gemm_multi(
    GSmem& sm, const __half* __restrict__ A, const __half* __restrict__ W,
    int bn, int m0, int phase, Epi epi)
{
    const int tid = threadIdx.x;
    const uint32_t sB = (uint32_t)__cvta_generic_to_shared(sm.B);
    const uint32_t sA = (uint32_t)__cvta_generic_to_shared(sm.A);

    #pragma unroll
    for (int i = 0; i < 16; i++) {
        int idx = tid + i * 256;
        int r = idx >> 5, g = idx & 31;
        cp16(sB + (uint32_t)(r * SB_STR + g * 8) * 2,
             W + (size_t)(bn + r) * 256 + g * 8);
    }
    cp_commit();

    auto tileOf = [&](int g) { return m0 + (((g >> 3) + phase) & (MTILES - 1)); };

    auto issueA = [&](int g) {
        uint32_t dst = sA + (uint32_t)((g & 3) * BM * SA_STR) * 2;
        const int bm = tileOf(g) * BM;
        const int k0 = (g & 7) * 32;
        #pragma unroll
        for (int i = 0; i < 2; i++) {
            int idx = tid + i * 256;
            int r = idx >> 2, gg = idx & 3;
            cp16(dst + (uint32_t)(r * SA_STR + gg * 8) * 2,
                 A + (size_t)(bm + r) * 256 + k0 + gg * 8);
        }
        cp_commit();
    };
    issueA(0); issueA(1); issueA(2);

    const int lane = tid & 31;
    const int wm = (tid >> 5) & 1, wn = tid >> 6;

    const int a_row = wm * 64 + (lane & 7) + ((lane >> 3) & 1) * 8;
    const int a_col = (lane >> 4) * 8;
    const int b_row = wn * 32 + (lane >> 4) * 8 + (lane & 7);
    const int b_col = ((lane >> 3) & 1) * 8;

    float acc[4][4][4] = {};

    auto compute = [&](int g) {
        const uint32_t aBase = sA + (uint32_t)((g & 3) * BM * SA_STR) * 2;
        const uint32_t bBase = sB + (uint32_t)((g & 7) * 32) * 2;
        #pragma unroll
        for (int ks = 0; ks < 2; ks++) {
            const int kb = ks * 16;
            uint32_t af[4][4], bf[2][4];
            #pragma unroll
            for (int mt = 0; mt < 4; mt++)
                LDSM_X4(af[mt],
                        aBase + (uint32_t)((a_row + mt * 16) * SA_STR + kb + a_col) * 2);
            #pragma unroll
            for (int pr = 0; pr < 2; pr++)
                LDSM_X4(bf[pr],
                        bBase + (uint32_t)((b_row + pr * 16) * SB_STR + kb + b_col) * 2);
            #pragma unroll
            for (int mt = 0; mt < 4; mt++)
                #pragma unroll
                for (int nt = 0; nt < 4; nt++)
                    mma16816(acc[mt][nt], af[mt], &bf[nt >> 1][(nt & 1) * 2]);
        }
    };

    const int T = MTILES * 8;
    for (int g = 0; g < T; g++) {
        if (g < T - 3)       { cp_wait<2>(); __syncthreads(); issueA(g + 3); }
        else if (g == T - 3) { cp_wait<2>(); __syncthreads(); }
        else if (g == T - 2) { cp_wait<1>(); __syncthreads(); }
        else                 { cp_wait<0>(); __syncthreads(); }
        compute(g);
        if ((g & 7) == 7) {
            epi(tileOf(g) * BM, acc);
            #pragma unroll
            for (int i = 0; i < 4; i++)
                #pragma unroll
                for (int j = 0; j < 4; j++)
                    #pragma unroll
                    for (int e = 0; e < 4; e++) acc[i][j][e] = 0.f;
        }
    }
}

// ---------------- GEMM kernels ----------------
__global__ __launch_bounds__(256, 2) void qkv_hmma(
    const float* __restrict__ b0, const float* __restrict__ b1)
{
    extern __shared__ char smem_raw[];
    GSmem& sm = *(GSmem*)smem_raw;
    const int stream = blockIdx.z;
    const int bn = blockIdx.x * BN;
    const int m0 = blockIdx.y * MTILES;
    const int phase = ((blockIdx.x + blockIdx.y + blockIdx.z) & 1) * (MTILES / 2);

    const float* __restrict__ bias = stream ? b1 : b0;
    __half* __restrict__ O = g_lin[stream];
    const int lane = threadIdx.x & 31;
    const int wm = (threadIdx.x >> 5) & 1, wn = threadIdx.x >> 6;
    const float sc = (bn < 256) ? SCALE_F : 1.0f;

    gemm_multi(sm, g_A[stream], g_Wqkv[stream], bn, m0, phase,
        [&](int bm, float acc[4][4][4]) {
            #pragma unroll
            for (int mt = 0; mt < 4; mt++) {
                const int r = bm + wm * 64 + mt * 16 + (lane >> 2);
                #pragma unroll
                for (int nt = 0; nt < 4; nt++) {
                    const int col = bn + wn * 32 + nt * 8 + (lane & 3) * 2;
                    const float bx = bias[col], by = bias[col + 1];
                    float2 v0 = make_float2((acc[mt][nt][0] + bx) * sc,
                                            (acc[mt][nt][1] + by) * sc);
                    float2 v1 = make_float2((acc[mt][nt][2] + bx) * sc,
                                            (acc[mt][nt][3] + by) * sc);
                    *(__half2*)&O[(size_t)r * 768 + col]       = __float22half2_rn(v0);
                    *(__half2*)&O[(size_t)(r + 8) * 768 + col] = __float22half2_rn(v1);
                }
            }
        });
}

__global__ __launch_bounds__(256, 2) void proj_hmma(
    const float* __restrict__ bp0, const float* __restrict__ bp1,
    float* __restrict__ out)
{
    extern __shared__ char smem_raw[];
    GSmem& sm = *(GSmem*)smem_raw;
    const int p = blockIdx.z;
    const int bn = blockIdx.x * BN;
    const int m0 = blockIdx.y * MTILES;
    const int phase = ((blockIdx.x + blockIdx.y + blockIdx.z) & 1) * (MTILES / 2);

    const float* __restrict__ bias = p ? bp1 : bp0;
    float* __restrict__ O = out + (size_t)p * SZ_AO;
    const int lane = threadIdx.x & 31;
    const int wm = (threadIdx.x >> 5) & 1, wn = threadIdx.x >> 6;

    gemm_multi(sm, g_aob[p], g_Wproj[p], bn, m0, phase,
        [&](int bm, float acc[4][4][4]) {
            #pragma unroll
            for (int mt = 0; mt < 4; mt++) {
                const int r = bm + wm * 64 + mt * 16 + (lane >> 2);
                #pragma unroll
                for (int nt = 0; nt < 4; nt++) {
                    const int col = bn + wn * 32 + nt * 8 + (lane & 3) * 2;
                    const float bx = bias[col], by = bias[col + 1];
                    float2 v0 = { acc[mt][nt][0] + bx, acc[mt][nt][1] + by };
                    float2 v1 = { acc[mt][nt][2] + bx, acc[mt][nt][3] + by };
                    *(float2*)&O[(size_t)r * 256 + col]       = v0;
                    *(float2*)&O[(size_t)(r + 8) * 256 + col] = v1;
                }
            }
        });
}

// ---------------- conversion / precompute kernels ----------------
__global__ __launch_bounds__(256) void conv_in(
    const float* __restrict__ x, const float* __restrict__ rgb)
{
    const int s = blockIdx.y;
    const float* __restrict__ src = s ? rgb : x;
    size_t idx = ((size_t)blockIdx.x * 256 + threadIdx.x) * 4;
    float4 v = *(const float4*)(src + idx);
    *(__half2*)&g_A[s][idx]     = __float22half2_rn(make_float2(v.x, v.y));
    *(__half2*)&g_A[s][idx + 2] = __float22half2_rn(make_float2(v.z, v.w));
}

__global__ __launch_bounds__(256) void conv_w(
    const float* __restrict__ w_qkv, const float* __restrict__ w_qkv_rgb,
    const float* __restrict__ w_proj, const float* __restrict__ w_proj_rgb)
{
    const int which = blockIdx.y;
    const float* src; __half* dst; int NC;
    switch (which) {
        case 0: src = w_qkv;       dst = g_Wqkv[0];  NC = 768; break;
        case 1: src = w_qkv_rgb;   dst = g_Wqkv[1];  NC = 768; break;
        case 2: src = w_proj;      dst = g_Wproj[0]; NC = 256; break;
        default: src = w_proj_rgb; dst = g_Wproj[1]; NC = 256; break;
    }
    int idx = blockIdx.x * 256 + threadIdx.x;
    if (idx >= 256 * NC) return;
    int k = idx / NC, n = idx % NC;
    dst[(size_t)n * 256 + k] = __float2half_rn(src[idx]);
}

// bias+mask -> fp16, padded row stride 56 (pad zeroed)
__global__ __launch_bounds__(256) void prep_bm(
    const float* __restrict__ mask, const float* __restrict__ bias_table,
    const int* __restrict__ rel_idx)
{
    const int w = blockIdx.x, h = blockIdx.y;
    __half* __restrict__ dst = g_bmh + (size_t)(w * H_ + h) * (N_ * BM_STRIDE);
    const float* __restrict__ msk = mask + (size_t)w * NN2;
    for (int idx = threadIdx.x; idx < N_ * BM_STRIDE; idx += 256) {
        int r = idx / BM_STRIDE, c = idx - r * BM_STRIDE;
        float v = (c < N_) ? (bias_table[rel_idx[r * N_ + c] * H_ + h]
                              + msk[r * N_ + c]) : 0.f;
        dst[idx] = __float2half_rn(v);
    }
}

// ---------------- fused attention (HMMA, both paths per block) --------------
__global__ __launch_bounds__(256) void attn_kernel()
{
    const int b = blockIdx.x, h = blockIdx.y;
    const int tid = threadIdx.x;
    const int grp = tid >> 7;            // 0 or 1 = path p
    const int gt  = tid & 127;

    const int p = grp;
    const int qs = p ^ 1, kv = p;
    const __half* __restrict__ qb = g_lin[qs] + (size_t)b * N_ * 768 + h * 32;
    const __half* __restrict__ kb = g_lin[kv] + (size_t)b * N_ * 768 + 256 + h * 32;
    const __half* __restrict__ vb = g_lin[kv] + (size_t)b * N_ * 768 + 512 + h * 32;
    const __half* __restrict__ bmh =
        g_bmh + (size_t)((b & (NW_ - 1)) * H_ + h) * (N_ * BM_STRIDE);

    __shared__ __align__(16) __half Qs[2][64 * 40];
    __shared__ __align__(16) __half Ks[2][64 * 40];
    __shared__ __align__(16) __half Vs[2][64 * 40];
    __shared__ __align__(16) __half P [2][64 * 72];

    for (int i = gt; i < N_ * 8; i += 128) {
        int n = i >> 3, dp = (i & 7) * 4;
        *(uint2*)&Qs[grp][n * 40 + dp] = *(const uint2*)(qb + n * 768 + dp);
        *(uint2*)&Ks[grp][n * 40 + dp] = *(const uint2*)(kb + n * 768 + dp);
        *(uint2*)&Vs[grp][n * 40 + dp] = *(const uint2*)(vb + n * 768 + dp);
    }
    for (int i = gt; i < 15 * 40; i += 128)
        Vs[grp][49 * 40 + i] = __ushort_as_half(0);
    {
        int r = gt >> 1, c = (gt & 1) * 4;
        *(uint2*)&P[grp][r * 72 + 56 + c] = make_uint2(0u, 0u);
    }
    __syncthreads();

    const int lane = tid & 31, w = (tid >> 5) & 3;
    const uint32_t sQ = (uint32_t)__cvta_generic_to_shared(Qs[grp]);
    const uint32_t sK = (uint32_t)__cvta_generic_to_shared(Ks[grp]);
    const uint32_t sV = (uint32_t)__cvta_generic_to_shared(Vs[grp]);
    const uint32_t sP = (uint32_t)__cvta_generic_to_shared(P[grp]);

    const int xr = (lane & 7) + ((lane >> 3) & 1) * 8;
    const int xc = (lane >> 4) * 8;
    const int kr = (lane >> 4) * 8 + (lane & 7);
    const int kc = ((lane >> 3) & 1) * 8;

    float acc[7][4] = {};
    #pragma unroll
    for (int ks = 0; ks < 2; ks++) {
        const int kb16 = ks * 16;
        uint32_t aq[4];
        LDSM_X4(aq, sQ + (uint32_t)((w * 16 + xr) * 40 + kb16 + xc) * 2);
        uint32_t bk[4][4];
        #pragma unroll
        for (int pr = 0; pr < 4; pr++)
            LDSM_X4(bk[pr], sK + (uint32_t)((pr * 16 + kr) * 40 + kb16 + kc) * 2);
        #pragma unroll
        for (int nt = 0; nt < 7; nt++)
            mma16816(acc[nt], aq, &bk[nt >> 1][(nt & 1) * 2]);
    }

    // ---- bias+mask add (fp16 half2 gathers); cols >= 49 assigned -1e30 ----
    const int r0 = w * 16 + (lane >> 2);
    const int c0 = (lane & 3) * 2;
    #pragma unroll
    for (int nt = 0; nt < 7; nt++) {
        const int col = nt * 8 + c0;
        #pragma unroll
        for (int er = 0; er < 2; er++) {
            const int rr = r0 + er * 8;
            if (rr < N_ && col + 1 < N_) {
                __half2 hv = *(const __half2*)&bmh[rr * BM_STRIDE + col];
                acc[nt][er * 2 + 0] += __half2float(__low2half(hv));
                acc[nt][er * 2 + 1] += __half2float(__high2half(hv));
            } else {
                if (col < N_) {
                    if (rr < N_)
                        acc[nt][er * 2] += __half2float(bmh[rr * BM_STRIDE + col]);
                } else acc[nt][er * 2] = -1e30f;
                if (col + 1 >= N_) acc[nt][er * 2 + 1] = -1e30f;
            }
        }
    }

    float mx0 = -1e30f, mx1 = -1e30f;
    #pragma unroll
    for (int nt = 0; nt < 7; nt++) {
        mx0 = fmaxf(mx0, fmaxf(acc[nt][0], acc[nt][1]));
        mx1 = fmaxf(mx1, fmaxf(acc[nt][2], acc[nt][3]));
    }
    mx0 = fmaxf(mx0, __shfl_xor_sync(~0u, mx0, 1));
    mx0 = fmaxf(mx0, __shfl_xor_sync(~0u, mx0, 2));
    mx1 = fmaxf(mx1, __shfl_xor_sync(~0u, mx1, 1));
    mx1 = fmaxf(mx1, __shfl_xor_sync(~0u, mx1, 2));

    float s0 = 0.f, s1 = 0.f;
    #pragma unroll
    for (int nt = 0; nt < 7; nt++) {
        acc[nt][0] = __expf(acc[nt][0] - mx0);
        acc[nt][1] = __expf(acc[nt][1] - mx0);
        acc[nt][2] = __expf(acc[nt][2] - mx1);
        acc[nt][3] = __expf(acc[nt][3] - mx1);
        s0 += acc[nt][0] + acc[nt][1];
        s1 += acc[nt][2] + acc[nt][3];
    }
    s0 += __shfl_xor_sync(~0u, s0, 1);
    s0 += __shfl_xor_sync(~0u, s0, 2);
    s1 += __shfl_xor_sync(~0u, s1, 1);
    s1 += __shfl_xor_sync(~0u, s1, 2);
    const float inv0 = 1.f / s0, inv1 = 1.f / s1;

    #pragma unroll
    for (int nt = 0; nt < 7; nt++) {
        const int col = nt * 8 + c0;
        *(__half2*)&P[grp][r0 * 72 + col] =
            __float22half2_rn(make_float2(acc[nt][0] * inv0, acc[nt][1] * inv0));
        *(__half2*)&P[grp][(r0 + 8) * 72 + col] =
            __float22half2_rn(make_float2(acc[nt][2] * inv1, acc[nt][3] * inv1));
    }
    __syncwarp();

    float o[4][4] = {};
    #pragma unroll
    for (int ks = 0; ks < 4; ks++) {
        uint32_t ap[4];
        LDSM_X4(ap, sP + (uint32_t)((w * 16 + xr) * 72 + ks * 16 + xc) * 2);
        uint32_t bv[2][4];
        #pragma unroll
        for (int pr = 0; pr < 2; pr++)
            LDSM_X4_T(bv[pr], sV + (uint32_t)((ks * 16 + xr) * 40 + pr * 16 + xc) * 2);
        #pragma unroll
        for (int nt = 0; nt < 4; nt++)
            mma16816(o[nt], ap, &bv[nt >> 1][(nt & 1) * 2]);
    }

    __half* __restrict__ dstBase = &g_aob[p][((size_t)b * N_) * 256 + h * 32];
    #pragma unroll
    for (int nt = 0; nt < 4; nt++) {
        const int d = nt * 8 + c0;
        if (r0 < N_)
            *(__half2*)&dstBase[(size_t)r0 * 256 + d] =
                __float22half2_rn(make_float2(o[nt][0], o[nt][1]));
        if (r0 + 8 < N_)
            *(__half2*)&dstBase[(size_t)(r0 + 8) * 256 + d] =
                __float22half2_rn(make_float2(o[nt][2], o[nt][3]));
    }
}

// ---------------- host launcher ----------------
extern "C" void kernel_launch(void* const* d_in, const int* in_sizes, int n_in,
                              void* d_out, int out_size)
{
    const float* x          = (const float*)d_in[0];
    const float* rgb        = (const float*)d_in[1];
    const float* mask       = (const float*)d_in[2];
    const float* w_qkv      = (const float*)d_in[3];
    const float* b_qkv      = (const float*)d_in[4];
    const float* w_qkv_rgb  = (const float*)d_in[5];
    const float* b_qkv_rgb  = (const float*)d_in[6];
    const float* bias_table = (const float*)d_in[7];
    const float* w_proj     = (const float*)d_in[8];
    const float* b_proj     = (const float*)d_in[9];
    const float* w_proj_rgb = (const float*)d_in[10];
    const float* b_proj_rgb = (const float*)d_in[11];
    const int*   rel_idx    = (const int*)d_in[12];
    float* out = (float*)d_out;

    cudaFuncSetAttribute(qkv_hmma,  cudaFuncAttributeMaxDynamicSharedMemorySize, SMEM_SZ);
    cudaFuncSetAttribute(proj_hmma, cudaFuncAttributeMaxDynamicSharedMemorySize, SMEM_SZ);

    conv_w<<<dim3(768, 4), 256>>>(w_qkv, w_qkv_rgb, w_proj, w_proj_rgb);
    prep_bm<<<dim3(NW_, H_), 256>>>(mask, bias_table, rel_idx);
    conv_in<<<dim3(MT / 4, 2), 256>>>(x, rgb);

    qkv_hmma<<<dim3(768 / BN, 1568 / MTILES, 2), 256, SMEM_SZ>>>(b_qkv, b_qkv_rgb);

    attn_kernel<<<dim3(B_, H_), 256>>>();

    proj_hmma<<<dim3(256 / BN, 1568 / MTILES, 2), 256, SMEM_SZ>>>(b_proj, b_proj_rgb, out);
}